// round 6
// baseline (speedup 1.0000x reference)
#include <cuda_runtime.h>
#include <cuda_bf16.h>
#include <cstdint>

#define NN 50000
#define HID 128
#define INDIM 16
#define OUTDIM 4
#define MAXE 600000
#define SCAN_CHUNK 1024
#define MAX_SCAN_BLOCKS 128
#define TSTRIDE 40    // per-chunk tile row stride (bf16 elems)
#define A0STRIDE 136  // full-K persistent A0 tile row stride (bf16 elems)

// fused-kernel dynamic smem layout (bytes)
#define FOFF_A0HI 0
#define FOFF_A0LO 34816
#define FOFF_A1HI 69632
#define FOFF_A1LO 79872
#define FOFF_BHI  90112
#define FOFF_BLO  100352
#define FOFF_WH   110592
#define FOFF_BH   112640
#define FOFF_RED  69632   /* reuse A1 region after MMAs */
#define FSM_TOTAL 112656

// ---- scratch (static device globals; no runtime allocation) ----
__device__ float g_agg[NN * INDIM];
__device__ float g_hA[NN * HID];
__device__ float g_hB[NN * HID];
__device__ __nv_bfloat16 g_wHi[4][HID * HID];  // Wl2,Wr2,Wl3,Wr3 splits
__device__ __nv_bfloat16 g_wLo[4][HID * HID];
__device__ int   g_src[MAXE];
__device__ int   g_dst[MAXE];
__device__ int   g_csrc[MAXE];
__device__ int   g_deg[NN];
__device__ int   g_rowstart[NN + 1];
__device__ int   g_cursor[NN];
__device__ int   g_blocksum[MAX_SCAN_BLOCKS];
__device__ int   g_blockoff[MAX_SCAN_BLOCKS];
__device__ int   g_is64;

// ================= helpers =================
__device__ __forceinline__ uint32_t smem_u32(const void* p) {
    uint32_t a;
    asm("{ .reg .u64 t; cvta.to.shared.u64 t, %1; cvt.u32.u64 %0, t; }" : "=r"(a) : "l"(p));
    return a;
}

#define LDMX4(r, a)                                                            \
    asm volatile("ldmatrix.sync.aligned.m8n8.x4.shared.b16 {%0,%1,%2,%3}, [%4];" \
                 : "=r"((r)[0]), "=r"((r)[1]), "=r"((r)[2]), "=r"((r)[3])      \
                 : "r"(a))

__device__ __forceinline__ void mma16816(float* c, const uint32_t* a, const uint32_t* b) {
    asm volatile(
        "mma.sync.aligned.m16n8k16.row.col.f32.bf16.bf16.f32 "
        "{%0,%1,%2,%3}, {%4,%5,%6,%7}, {%8,%9}, {%0,%1,%2,%3};"
        : "+f"(c[0]), "+f"(c[1]), "+f"(c[2]), "+f"(c[3])
        : "r"(a[0]), "r"(a[1]), "r"(a[2]), "r"(a[3]), "r"(b[0]), "r"(b[1]));
}

__device__ __forceinline__ void split2(float v, __nv_bfloat16& hi, __nv_bfloat16& lo) {
    hi = __float2bfloat16(v);
    lo = __float2bfloat16(v - __bfloat162float(hi));
}
__device__ __forceinline__ uint32_t pack2(__nv_bfloat16 a, __nv_bfloat16 b) {
    __nv_bfloat162 t = __halves2bfloat162(a, b);
    return *reinterpret_cast<uint32_t*>(&t);
}

// ================= CSR build =================
__global__ void detect_kernel(const int* __restrict__ w) {
    __shared__ int anynz;
    if (threadIdx.x == 0) anynz = 0;
    __syncthreads();
    if (w[2 * threadIdx.x + 1] != 0) atomicOr(&anynz, 1);
    __syncthreads();
    if (threadIdx.x == 0) g_is64 = anynz ? 0 : 1;
}

__global__ void zero_i_kernel(int* __restrict__ p, int n) {
    int i = blockIdx.x * blockDim.x + threadIdx.x;
    if (i < n) p[i] = 0;
}

__global__ void convert_kernel(const int* __restrict__ w, int E) {
    int i = blockIdx.x * blockDim.x + threadIdx.x;
    if (i >= E) return;
    int s, d;
    if (g_is64) { s = w[2 * i]; d = w[2 * (E + i)]; }
    else        { s = w[i];     d = w[E + i];       }
    g_src[i] = s;
    g_dst[i] = d;
    atomicAdd(&g_deg[d], 1);
}

__device__ __forceinline__ void block_scan_1024(int& thread_sum, int& thread_excl, int* warp_buf) {
    int t = threadIdx.x;
    int lane = t & 31, w = t >> 5;
    int v = thread_sum;
#pragma unroll
    for (int off = 1; off < 32; off <<= 1) {
        int u = __shfl_up_sync(0xffffffffu, v, off);
        if (lane >= off) v += u;
    }
    if (lane == 31) warp_buf[w] = v;
    __syncthreads();
    if (w == 0) {
        int ws = (lane < 8) ? warp_buf[lane] : 0;
#pragma unroll
        for (int off = 1; off < 8; off <<= 1) {
            int u = __shfl_up_sync(0xffffffffu, ws, off);
            if (lane >= off) ws += u;
        }
        if (lane < 8) warp_buf[lane] = ws;
    }
    __syncthreads();
    thread_excl = v - thread_sum + (w > 0 ? warp_buf[w - 1] : 0);
}

__global__ void scan_phase1(int M) {
    __shared__ int warp_buf[8];
    int b = blockIdx.x, t = threadIdx.x;
    int base = b * SCAN_CHUNK + t * 4;
    int d[4] = {0, 0, 0, 0};
#pragma unroll
    for (int i = 0; i < 4; i++)
        if (base + i < M) d[i] = g_deg[base + i];
    int s = d[0] + d[1] + d[2] + d[3];
    int excl;
    block_scan_1024(s, excl, warp_buf);
    if (t == blockDim.x - 1) g_blocksum[b] = excl + s;
}

__global__ void scan_phase2(int NB) {
    __shared__ int buf[MAX_SCAN_BLOCKS];
    int t = threadIdx.x;
    if (t < NB) buf[t] = g_blocksum[t];
    __syncthreads();
    if (t == 0) {
        int run = 0;
        for (int i = 0; i < NB; i++) { int x = buf[i]; buf[i] = run; run += x; }
    }
    __syncthreads();
    if (t < NB) g_blockoff[t] = buf[t];
}

__global__ void scan_phase3(int M, int E) {
    __shared__ int warp_buf[8];
    int b = blockIdx.x, t = threadIdx.x;
    int base = b * SCAN_CHUNK + t * 4;
    int d[4] = {0, 0, 0, 0};
#pragma unroll
    for (int i = 0; i < 4; i++)
        if (base + i < M) d[i] = g_deg[base + i];
    int s = d[0] + d[1] + d[2] + d[3];
    int excl;
    block_scan_1024(s, excl, warp_buf);
    int run = excl + g_blockoff[b];
#pragma unroll
    for (int i = 0; i < 4; i++) {
        if (base + i < M) {
            g_rowstart[base + i] = run;
            g_cursor[base + i] = run;
            run += d[i];
        }
    }
    if (b == 0 && t == 0) g_rowstart[M] = E;
}

__global__ void fill_kernel(int E) {
    int i = blockIdx.x * blockDim.x + threadIdx.x;
    if (i >= E) return;
    int d = g_dst[i];
    int pos = atomicAdd(&g_cursor[d], 1);
    g_csrc[pos] = g_src[i];
}

// ================= weight split =================
__global__ void wsplit_kernel(const float* __restrict__ w, __nv_bfloat16* __restrict__ hi,
                              __nv_bfloat16* __restrict__ lo, int n) {
    int i = blockIdx.x * blockDim.x + threadIdx.x;
    if (i >= n) return;
    __nv_bfloat16 h, l;
    split2(w[i], h, l);
    hi[i] = h;
    lo[i] = l;
}

// ================= layer-1: 16-dim gather =================
__global__ void gather16_kernel(const float* __restrict__ x, float* __restrict__ agg, int M) {
    int gt = blockIdx.x * blockDim.x + threadIdx.x;
    int n = gt >> 2;
    if (n >= M) return;
    int q = gt & 3;
    int rs0 = g_rowstart[n], rs1 = g_rowstart[n + 1];
    float4 acc = make_float4(0.f, 0.f, 0.f, 0.f);
    for (int i = rs0; i < rs1; i++) {
        int s0 = g_csrc[i];
        float4 v = __ldg(reinterpret_cast<const float4*>(x + (size_t)s0 * INDIM) + q);
        acc.x += v.x; acc.y += v.y; acc.z += v.z; acc.w += v.w;
    }
    float sc = 1.0f / (float)max(rs1 - rs0, 1);
    acc.x *= sc; acc.y *= sc; acc.z *= sc; acc.w *= sc;
    reinterpret_cast<float4*>(agg + (size_t)n * INDIM)[q] = acc;
}

// ================= layer-1 FFMA GEMM (K=32) =================
template <int S>
__global__ void __launch_bounds__(256)
sage_gemm_kernel(const float* __restrict__ A0, const float* __restrict__ A1,
                 const float* __restrict__ W0, const float* __restrict__ W1,
                 const float* __restrict__ bias, float* __restrict__ C, int M) {
    __shared__ float As[8][128];
    __shared__ float Bs[8][128];

    const int tid = threadIdx.x;
    const int m0 = blockIdx.x * 128;
    const int lm = tid >> 1;
    const int kq = (tid & 1) * 4;
    const int node = m0 + lm;
    const int tr = tid >> 4;
    const int tc = tid & 15;

    float acc[8][8];
#pragma unroll
    for (int i = 0; i < 8; i++)
#pragma unroll
        for (int j = 0; j < 8; j++) acc[i][j] = 0.f;

    const int K = 2 * S;
#pragma unroll 2
    for (int k0 = 0; k0 < K; k0 += 8) {
        const bool half = (k0 >= S);
        const float* Ab = half ? A1 : A0;
        const float* Wb = half ? W1 : W0;
        const int koff = (half ? k0 - S : k0) + kq;

        float4 va = make_float4(0.f, 0.f, 0.f, 0.f);
        if (node < M)
            va = *reinterpret_cast<const float4*>(Ab + (size_t)node * S + koff);
        float4 vb = *reinterpret_cast<const float4*>(Wb + (size_t)lm * S + koff);

        __syncthreads();
        As[kq + 0][lm] = va.x;
        As[kq + 1][lm] = va.y;
        As[kq + 2][lm] = va.z;
        As[kq + 3][lm] = va.w;
        Bs[kq + 0][lm] = vb.x;
        Bs[kq + 1][lm] = vb.y;
        Bs[kq + 2][lm] = vb.z;
        Bs[kq + 3][lm] = vb.w;
        __syncthreads();

#pragma unroll
        for (int k = 0; k < 8; k++) {
            float4 a0 = *reinterpret_cast<float4*>(&As[k][tr * 8]);
            float4 a1 = *reinterpret_cast<float4*>(&As[k][tr * 8 + 4]);
            float4 b0 = *reinterpret_cast<float4*>(&Bs[k][tc * 8]);
            float4 b1 = *reinterpret_cast<float4*>(&Bs[k][tc * 8 + 4]);
            float av[8] = {a0.x, a0.y, a0.z, a0.w, a1.x, a1.y, a1.z, a1.w};
            float bv[8] = {b0.x, b0.y, b0.z, b0.w, b1.x, b1.y, b1.z, b1.w};
#pragma unroll
            for (int i = 0; i < 8; i++)
#pragma unroll
                for (int j = 0; j < 8; j++) acc[i][j] += av[i] * bv[j];
        }
    }

    float4 bb0 = *reinterpret_cast<const float4*>(bias + tc * 8);
    float4 bb1 = *reinterpret_cast<const float4*>(bias + tc * 8 + 4);
    float bb[8] = {bb0.x, bb0.y, bb0.z, bb0.w, bb1.x, bb1.y, bb1.z, bb1.w};
#pragma unroll
    for (int i = 0; i < 8; i++) {
        int n = m0 + tr * 8 + i;
        if (n < M) {
            float4 o0, o1;
            o0.x = fmaxf(acc[i][0] + bb[0], 0.f);
            o0.y = fmaxf(acc[i][1] + bb[1], 0.f);
            o0.z = fmaxf(acc[i][2] + bb[2], 0.f);
            o0.w = fmaxf(acc[i][3] + bb[3], 0.f);
            o1.x = fmaxf(acc[i][4] + bb[4], 0.f);
            o1.y = fmaxf(acc[i][5] + bb[5], 0.f);
            o1.z = fmaxf(acc[i][6] + bb[6], 0.f);
            o1.w = fmaxf(acc[i][7] + bb[7], 0.f);
            *reinterpret_cast<float4*>(C + (size_t)n * HID + tc * 8) = o0;
            *reinterpret_cast<float4*>(C + (size_t)n * HID + tc * 8 + 4) = o1;
        }
    }
}

// ================= fused gather + tensor-core SAGE layer (layers 2/3) =================
// Per block: gather mean-agg for its 128 nodes directly into persistent bf16 hi/lo
// smem tiles, then C = relu(agg.W0^T + h.W1^T + bias). If FINAL, additionally
// computes out = C.Wh^T + bh in-block and skips storing C.
template <bool FINAL>
__global__ void __launch_bounds__(256)
fused_sage_kernel(const float* __restrict__ hIn,
                  const __nv_bfloat16* __restrict__ W0hi, const __nv_bfloat16* __restrict__ W0lo,
                  const __nv_bfloat16* __restrict__ W1hi, const __nv_bfloat16* __restrict__ W1lo,
                  const float* __restrict__ bias, float* __restrict__ C,
                  const float* __restrict__ Wh, const float* __restrict__ bh,
                  float* __restrict__ out, int M) {
    extern __shared__ char fsm[];
    __nv_bfloat16* sA0hi = reinterpret_cast<__nv_bfloat16*>(fsm + FOFF_A0HI);
    __nv_bfloat16* sA0lo = reinterpret_cast<__nv_bfloat16*>(fsm + FOFF_A0LO);
    __nv_bfloat16* sA1hi = reinterpret_cast<__nv_bfloat16*>(fsm + FOFF_A1HI);
    __nv_bfloat16* sA1lo = reinterpret_cast<__nv_bfloat16*>(fsm + FOFF_A1LO);
    __nv_bfloat16* sBhi  = reinterpret_cast<__nv_bfloat16*>(fsm + FOFF_BHI);
    __nv_bfloat16* sBlo  = reinterpret_cast<__nv_bfloat16*>(fsm + FOFF_BLO);
    float* sWh = reinterpret_cast<float*>(fsm + FOFF_WH);
    float* sbh = reinterpret_cast<float*>(fsm + FOFF_BH);

    const int tid = threadIdx.x;
    const int wid = tid >> 5;
    const int lane = tid & 31;
    const int wm = wid & 3;
    const int wn = wid >> 2;
    const int m0 = blockIdx.x * 128;

    if (FINAL) {
        for (int u = tid; u < OUTDIM * HID; u += 256) sWh[u] = Wh[u];
        if (tid < OUTDIM) sbh[tid] = bh[tid];
    }

    // ---- phase 1: fused CSR mean-gather into persistent full-K A0 hi/lo tiles ----
    {
        int rbase = wid * 16;
#pragma unroll 1
        for (int rr = 0; rr < 16; rr++) {
            int r = rbase + rr;
            int node = m0 + r;
            float4 a = make_float4(0.f, 0.f, 0.f, 0.f);
            if (node < M) {
                int rs0 = g_rowstart[node], rs1 = g_rowstart[node + 1];
                int i = rs0;
                for (; i + 2 <= rs1; i += 2) {
                    int s0 = g_csrc[i + 0];
                    int s1 = g_csrc[i + 1];
                    float4 v0 = __ldg(reinterpret_cast<const float4*>(hIn + (size_t)s0 * HID) + lane);
                    float4 v1 = __ldg(reinterpret_cast<const float4*>(hIn + (size_t)s1 * HID) + lane);
                    a.x += v0.x + v1.x;
                    a.y += v0.y + v1.y;
                    a.z += v0.z + v1.z;
                    a.w += v0.w + v1.w;
                }
                for (; i < rs1; i++) {
                    int s0 = g_csrc[i];
                    float4 v0 = __ldg(reinterpret_cast<const float4*>(hIn + (size_t)s0 * HID) + lane);
                    a.x += v0.x; a.y += v0.y; a.z += v0.z; a.w += v0.w;
                }
                float sc = 1.0f / (float)max(rs1 - rs0, 1);
                a.x *= sc; a.y *= sc; a.z *= sc; a.w *= sc;
            }
            __nv_bfloat16 h0, l0, h1, l1, h2, l2, h3, l3;
            split2(a.x, h0, l0);
            split2(a.y, h1, l1);
            split2(a.z, h2, l2);
            split2(a.w, h3, l3);
            uint2 ph, pl;
            ph.x = pack2(h0, h1); ph.y = pack2(h2, h3);
            pl.x = pack2(l0, l1); pl.y = pack2(l2, l3);
            *reinterpret_cast<uint2*>(sA0hi + r * A0STRIDE + lane * 4) = ph;
            *reinterpret_cast<uint2*>(sA0lo + r * A0STRIDE + lane * 4) = pl;
        }
    }
    __syncthreads();

    const uint32_t uA0hi = smem_u32(sA0hi);
    const uint32_t uA0lo = smem_u32(sA0lo);
    const uint32_t uA1hi = smem_u32(sA1hi);
    const uint32_t uA1lo = smem_u32(sA1lo);
    const uint32_t uBhi = smem_u32(sBhi);
    const uint32_t uBlo = smem_u32(sBlo);

    float acc[2][8][4];
#pragma unroll
    for (int i = 0; i < 2; i++)
#pragma unroll
        for (int j = 0; j < 8; j++)
#pragma unroll
            for (int k = 0; k < 4; k++) acc[i][j][k] = 0.f;

    const int arow = wm * 32 + (lane & 15);
    const int akof = (lane & 16) ? 8 : 0;
    const int nrow0 = wn * 64 + (lane & 7) + ((lane & 16) ? 8 : 0);
    const int nkof = (lane & 8) ? 8 : 0;

    // ---- phase 2: MMA mainloop, K = 2*128 in chunks of 32 ----
#pragma unroll
    for (int chunk = 0; chunk < 8; chunk++) {
        const bool selfp = (chunk >= 4);
        const __nv_bfloat16* WH = selfp ? W1hi : W0hi;
        const __nv_bfloat16* WL = selfp ? W1lo : W0lo;
        const int koff = (chunk & 3) * 32;

        __syncthreads();
        if (selfp) {
            // stage self-path A1 tile (fp32 -> hi/lo split)
#pragma unroll
            for (int i = 0; i < 4; i++) {
                int u = tid + i * 256;
                int row = u >> 3;
                int q = (u & 7) * 4;
                float4 v = make_float4(0.f, 0.f, 0.f, 0.f);
                int node = m0 + row;
                if (node < M)
                    v = *reinterpret_cast<const float4*>(hIn + (size_t)node * HID + koff + q);
                __nv_bfloat16 h0, l0, h1, l1, h2, l2, h3, l3;
                split2(v.x, h0, l0);
                split2(v.y, h1, l1);
                split2(v.z, h2, l2);
                split2(v.w, h3, l3);
                int so = row * TSTRIDE + q;
                uint2 ph, pl;
                ph.x = pack2(h0, h1); ph.y = pack2(h2, h3);
                pl.x = pack2(l0, l1); pl.y = pack2(l2, l3);
                *reinterpret_cast<uint2*>(sA1hi + so) = ph;
                *reinterpret_cast<uint2*>(sA1lo + so) = pl;
            }
        }
        // stage B tile
#pragma unroll
        for (int i = 0; i < 2; i++) {
            int u = tid + i * 256;
            int row = u >> 2;
            int c = (u & 3) * 8;
            uint4 vh = *reinterpret_cast<const uint4*>(WH + (size_t)row * HID + koff + c);
            uint4 vl = *reinterpret_cast<const uint4*>(WL + (size_t)row * HID + koff + c);
            int so = row * TSTRIDE + c;
            *reinterpret_cast<uint4*>(sBhi + so) = vh;
            *reinterpret_cast<uint4*>(sBlo + so) = vl;
        }
        __syncthreads();

#pragma unroll
        for (int ks = 0; ks < 2; ks++) {
            const int k0 = ks * 16;
            uint32_t ahi[2][4], alo[2][4];
#pragma unroll
            for (int mi = 0; mi < 2; mi++) {
                uint32_t off;
                if (!selfp)
                    off = uA0hi + ((arow + mi * 16) * A0STRIDE + koff + k0 + akof) * 2;
                else
                    off = uA1hi + ((arow + mi * 16) * TSTRIDE + k0 + akof) * 2;
                LDMX4(ahi[mi], off);
                uint32_t offl;
                if (!selfp)
                    offl = uA0lo + ((arow + mi * 16) * A0STRIDE + koff + k0 + akof) * 2;
                else
                    offl = uA1lo + ((arow + mi * 16) * TSTRIDE + k0 + akof) * 2;
                LDMX4(alo[mi], offl);
            }
#pragma unroll
            for (int np = 0; np < 4; np++) {
                uint32_t boff = ((nrow0 + np * 16) * TSTRIDE + k0 + nkof) * 2;
                uint32_t bh4[4], bl4[4];
                LDMX4(bh4, uBhi + boff);
                LDMX4(bl4, uBlo + boff);
#pragma unroll
                for (int mi = 0; mi < 2; mi++) {
#pragma unroll
                    for (int na = 0; na < 2; na++) {
                        float* c = acc[mi][np * 2 + na];
                        mma16816(c, ahi[mi], &bh4[na * 2]);
                        mma16816(c, ahi[mi], &bl4[na * 2]);
                        mma16816(c, alo[mi], &bh4[na * 2]);
                    }
                }
            }
        }
    }

    // ---- phase 3: epilogue ----
    if (!FINAL) {
#pragma unroll
        for (int mi = 0; mi < 2; mi++) {
            int row0 = m0 + wm * 32 + mi * 16 + (lane >> 2);
            int row1 = row0 + 8;
#pragma unroll
            for (int ni = 0; ni < 8; ni++) {
                int col = wn * 64 + ni * 8 + 2 * (lane & 3);
                float b0 = __ldg(bias + col);
                float b1 = __ldg(bias + col + 1);
                float* c = acc[mi][ni];
                if (row0 < M) {
                    float2 v;
                    v.x = fmaxf(c[0] + b0, 0.f);
                    v.y = fmaxf(c[1] + b1, 0.f);
                    *reinterpret_cast<float2*>(C + (size_t)row0 * HID + col) = v;
                }
                if (row1 < M) {
                    float2 v;
                    v.x = fmaxf(c[2] + b0, 0.f);
                    v.y = fmaxf(c[3] + b1, 0.f);
                    *reinterpret_cast<float2*>(C + (size_t)row1 * HID + col) = v;
                }
            }
        }
    } else {
        // fused final projection: out[row][j] = sum_col relu(acc+bias)*Wh[j][col] + bh[j]
        __syncthreads();   // all smem MMA reads done; safe to reuse red region
        float* red = reinterpret_cast<float*>(fsm + FOFF_RED);   // [128][4][2]
#pragma unroll
        for (int mi = 0; mi < 2; mi++) {
            float p0[OUTDIM] = {0.f, 0.f, 0.f, 0.f};
            float p1[OUTDIM] = {0.f, 0.f, 0.f, 0.f};
#pragma unroll
            for (int ni = 0; ni < 8; ni++) {
                int col = wn * 64 + ni * 8 + 2 * (lane & 3);
                float b0 = __ldg(bias + col);
                float b1 = __ldg(bias + col + 1);
                float* c = acc[mi][ni];
                float v0 = fmaxf(c[0] + b0, 0.f);
                float v1 = fmaxf(c[1] + b1, 0.f);
                float v2 = fmaxf(c[2] + b0, 0.f);
                float v3 = fmaxf(c[3] + b1, 0.f);
#pragma unroll
                for (int j = 0; j < OUTDIM; j++) {
                    float w0 = sWh[j * HID + col];
                    float w1 = sWh[j * HID + col + 1];
                    p0[j] += v0 * w0 + v1 * w1;
                    p1[j] += v2 * w0 + v3 * w1;
                }
            }
            // reduce across the 4 lanes of the quad (lane&3 = col groups)
#pragma unroll
            for (int j = 0; j < OUTDIM; j++) {
                p0[j] += __shfl_xor_sync(0xffffffffu, p0[j], 1);
                p0[j] += __shfl_xor_sync(0xffffffffu, p0[j], 2);
                p1[j] += __shfl_xor_sync(0xffffffffu, p1[j], 1);
                p1[j] += __shfl_xor_sync(0xffffffffu, p1[j], 2);
            }
            if ((lane & 3) == 0) {
                int r0 = wm * 32 + mi * 16 + (lane >> 2);
                int r1 = r0 + 8;
#pragma unroll
                for (int j = 0; j < OUTDIM; j++) {
                    red[r0 * 8 + j * 2 + wn] = p0[j];
                    red[r1 * 8 + j * 2 + wn] = p1[j];
                }
            }
        }
        __syncthreads();
        for (int u = tid; u < 128 * OUTDIM; u += 256) {
            int row = u >> 2;
            int j = u & 3;
            int node = m0 + row;
            if (node < M)
                out[(size_t)node * OUTDIM + j] = red[row * 8 + j * 2 + 0] + red[row * 8 + j * 2 + 1] + sbh[j];
        }
    }
}

// ---------------------------------------------------------------
extern "C" void kernel_launch(void* const* d_in, const int* in_sizes, int n_in,
                              void* d_out, int out_size) {
    (void)n_in; (void)out_size;
    const float* x   = (const float*)d_in[0];
    const int*   ei  = (const int*)d_in[1];
    const float* Wl1 = (const float*)d_in[2];
    const float* Wr1 = (const float*)d_in[3];
    const float* b1  = (const float*)d_in[4];
    const float* Wl2 = (const float*)d_in[5];
    const float* Wr2 = (const float*)d_in[6];
    const float* b2  = (const float*)d_in[7];
    const float* Wl3 = (const float*)d_in[8];
    const float* Wr3 = (const float*)d_in[9];
    const float* b3  = (const float*)d_in[10];
    const float* Wh  = (const float*)d_in[11];
    const float* bh  = (const float*)d_in[12];
    float* out = (float*)d_out;

    const int M = in_sizes[0] / INDIM;   // 50000
    const int E = in_sizes[1] / 2;       // 600000

    float *agg, *hA, *hB;
    int* deg;
    __nv_bfloat16 *wHi, *wLo;
    cudaGetSymbolAddress((void**)&agg, g_agg);
    cudaGetSymbolAddress((void**)&hA, g_hA);
    cudaGetSymbolAddress((void**)&hB, g_hB);
    cudaGetSymbolAddress((void**)&deg, g_deg);
    cudaGetSymbolAddress((void**)&wHi, g_wHi);
    cudaGetSymbolAddress((void**)&wLo, g_wLo);

    cudaFuncSetAttribute(fused_sage_kernel<false>,
                         cudaFuncAttributeMaxDynamicSharedMemorySize, FSM_TOTAL);
    cudaFuncSetAttribute(fused_sage_kernel<true>,
                         cudaFuncAttributeMaxDynamicSharedMemorySize, FSM_TOTAL);

    const int T = 256;
    const int NB = (M + SCAN_CHUNK - 1) / SCAN_CHUNK;

    // ---- CSR build ----
    detect_kernel<<<1, 64>>>(ei);
    zero_i_kernel<<<(M + T - 1) / T, T>>>(deg, M);
    convert_kernel<<<(E + T - 1) / T, T>>>(ei, E);
    scan_phase1<<<NB, 256>>>(M);
    scan_phase2<<<1, MAX_SCAN_BLOCKS>>>(NB);
    scan_phase3<<<NB, 256>>>(M, E);
    fill_kernel<<<(E + T - 1) / T, T>>>(E);

    // ---- weight splits ----
    const int WN = HID * HID;
    wsplit_kernel<<<(WN + T - 1) / T, T>>>(Wl2, wHi + 0 * WN, wLo + 0 * WN, WN);
    wsplit_kernel<<<(WN + T - 1) / T, T>>>(Wr2, wHi + 1 * WN, wLo + 1 * WN, WN);
    wsplit_kernel<<<(WN + T - 1) / T, T>>>(Wl3, wHi + 2 * WN, wLo + 2 * WN, WN);
    wsplit_kernel<<<(WN + T - 1) / T, T>>>(Wr3, wHi + 3 * WN, wLo + 3 * WN, WN);

    const int gemmBlocks = (M + 127) / 128;

    // ---- layer 1 (16 -> 128), FFMA ----
    gather16_kernel<<<((M * 4) + T - 1) / T, T>>>(x, agg, M);
    sage_gemm_kernel<INDIM><<<gemmBlocks, 256>>>(agg, x, Wl1, Wr1, b1, hA, M);

    // ---- layer 2 (128 -> 128), fused gather + mma ----
    fused_sage_kernel<false><<<gemmBlocks, 256, FSM_TOTAL>>>(
        hA, wHi + 0 * WN, wLo + 0 * WN, wHi + 1 * WN, wLo + 1 * WN,
        b2, hB, nullptr, nullptr, nullptr, M);

    // ---- layer 3 (128 -> 128) + final projection, fused ----
    fused_sage_kernel<true><<<gemmBlocks, 256, FSM_TOTAL>>>(
        hB, wHi + 2 * WN, wLo + 2 * WN, wHi + 3 * WN, wLo + 3 * WN,
        b3, nullptr, Wh, bh, out, M);
}

// round 8
// speedup vs baseline: 1.4065x; 1.4065x over previous
#include <cuda_runtime.h>
#include <cuda_bf16.h>
#include <cstdint>

#define NN 50000
#define HID 128
#define INDIM 16
#define OUTDIM 4
#define MAXE 600000
#define SCAN_CHUNK 1024
#define MAX_SCAN_BLOCKS 128
#define TSTRIDE 40    // per-chunk tile row stride (bf16 elems)
#define A0STRIDE 136  // full-K persistent A0 tile row stride (bf16 elems)

// fused-kernel dynamic smem layout (bytes)
#define FOFF_A0HI 0
#define FOFF_A0LO 34816
#define FOFF_A1HI 69632
#define FOFF_A1LO 79872
#define FOFF_BHI  90112
#define FOFF_BLO  100352
#define FOFF_WH   110592
#define FOFF_BH   112640
#define FOFF_RED  69632   /* reuse A1 region after MMAs */
#define FSM_TOTAL 112656

// ---- scratch (static device globals; no runtime allocation) ----
__device__ float g_agg[NN * INDIM];
__device__ float g_hA[NN * HID];
__device__ float g_hB[NN * HID];
__device__ __nv_bfloat16 g_wHi[4][HID * HID];  // Wl2,Wr2,Wl3,Wr3 splits
__device__ __nv_bfloat16 g_wLo[4][HID * HID];
__device__ int   g_src[MAXE];
__device__ int   g_dst[MAXE];
__device__ int   g_csrc[MAXE];
__device__ int   g_deg[NN];
__device__ int   g_rowstart[NN + 1];
__device__ int   g_cursor[NN];
__device__ int   g_blocksum[MAX_SCAN_BLOCKS];
__device__ int   g_blockoff[MAX_SCAN_BLOCKS];
__device__ int   g_is64;

// ================= helpers =================
__device__ __forceinline__ uint32_t smem_u32(const void* p) {
    uint32_t a;
    asm("{ .reg .u64 t; cvta.to.shared.u64 t, %1; cvt.u32.u64 %0, t; }" : "=r"(a) : "l"(p));
    return a;
}

#define LDMX4(r, a)                                                            \
    asm volatile("ldmatrix.sync.aligned.m8n8.x4.shared.b16 {%0,%1,%2,%3}, [%4];" \
                 : "=r"((r)[0]), "=r"((r)[1]), "=r"((r)[2]), "=r"((r)[3])      \
                 : "r"(a))

__device__ __forceinline__ void mma16816(float* c, const uint32_t* a, const uint32_t* b) {
    asm volatile(
        "mma.sync.aligned.m16n8k16.row.col.f32.bf16.bf16.f32 "
        "{%0,%1,%2,%3}, {%4,%5,%6,%7}, {%8,%9}, {%0,%1,%2,%3};"
        : "+f"(c[0]), "+f"(c[1]), "+f"(c[2]), "+f"(c[3])
        : "r"(a[0]), "r"(a[1]), "r"(a[2]), "r"(a[3]), "r"(b[0]), "r"(b[1]));
}

__device__ __forceinline__ void split2(float v, __nv_bfloat16& hi, __nv_bfloat16& lo) {
    hi = __float2bfloat16(v);
    lo = __float2bfloat16(v - __bfloat162float(hi));
}
__device__ __forceinline__ uint32_t pack2(__nv_bfloat16 a, __nv_bfloat16 b) {
    __nv_bfloat162 t = __halves2bfloat162(a, b);
    return *reinterpret_cast<uint32_t*>(&t);
}

// ================= CSR build =================
__global__ void detect_kernel(const int* __restrict__ w) {
    __shared__ int anynz;
    if (threadIdx.x == 0) anynz = 0;
    __syncthreads();
    if (w[2 * threadIdx.x + 1] != 0) atomicOr(&anynz, 1);
    __syncthreads();
    if (threadIdx.x == 0) g_is64 = anynz ? 0 : 1;
}

__global__ void zero_i_kernel(int* __restrict__ p, int n) {
    int i = blockIdx.x * blockDim.x + threadIdx.x;
    if (i < n) p[i] = 0;
}

__global__ void convert_kernel(const int* __restrict__ w, int E) {
    int i = blockIdx.x * blockDim.x + threadIdx.x;
    if (i >= E) return;
    int s, d;
    if (g_is64) { s = w[2 * i]; d = w[2 * (E + i)]; }
    else        { s = w[i];     d = w[E + i];       }
    g_src[i] = s;
    g_dst[i] = d;
    atomicAdd(&g_deg[d], 1);
}

__device__ __forceinline__ void block_scan_1024(int& thread_sum, int& thread_excl, int* warp_buf) {
    int t = threadIdx.x;
    int lane = t & 31, w = t >> 5;
    int v = thread_sum;
#pragma unroll
    for (int off = 1; off < 32; off <<= 1) {
        int u = __shfl_up_sync(0xffffffffu, v, off);
        if (lane >= off) v += u;
    }
    if (lane == 31) warp_buf[w] = v;
    __syncthreads();
    if (w == 0) {
        int ws = (lane < 8) ? warp_buf[lane] : 0;
#pragma unroll
        for (int off = 1; off < 8; off <<= 1) {
            int u = __shfl_up_sync(0xffffffffu, ws, off);
            if (lane >= off) ws += u;
        }
        if (lane < 8) warp_buf[lane] = ws;
    }
    __syncthreads();
    thread_excl = v - thread_sum + (w > 0 ? warp_buf[w - 1] : 0);
}

__global__ void scan_phase1(int M) {
    __shared__ int warp_buf[8];
    int b = blockIdx.x, t = threadIdx.x;
    int base = b * SCAN_CHUNK + t * 4;
    int d[4] = {0, 0, 0, 0};
#pragma unroll
    for (int i = 0; i < 4; i++)
        if (base + i < M) d[i] = g_deg[base + i];
    int s = d[0] + d[1] + d[2] + d[3];
    int excl;
    block_scan_1024(s, excl, warp_buf);
    if (t == blockDim.x - 1) g_blocksum[b] = excl + s;
}

__global__ void scan_phase2(int NB) {
    __shared__ int buf[MAX_SCAN_BLOCKS];
    int t = threadIdx.x;
    if (t < NB) buf[t] = g_blocksum[t];
    __syncthreads();
    if (t == 0) {
        int run = 0;
        for (int i = 0; i < NB; i++) { int x = buf[i]; buf[i] = run; run += x; }
    }
    __syncthreads();
    if (t < NB) g_blockoff[t] = buf[t];
}

__global__ void scan_phase3(int M, int E) {
    __shared__ int warp_buf[8];
    int b = blockIdx.x, t = threadIdx.x;
    int base = b * SCAN_CHUNK + t * 4;
    int d[4] = {0, 0, 0, 0};
#pragma unroll
    for (int i = 0; i < 4; i++)
        if (base + i < M) d[i] = g_deg[base + i];
    int s = d[0] + d[1] + d[2] + d[3];
    int excl;
    block_scan_1024(s, excl, warp_buf);
    int run = excl + g_blockoff[b];
#pragma unroll
    for (int i = 0; i < 4; i++) {
        if (base + i < M) {
            g_rowstart[base + i] = run;
            g_cursor[base + i] = run;
            run += d[i];
        }
    }
    if (b == 0 && t == 0) g_rowstart[M] = E;
}

__global__ void fill_kernel(int E) {
    int i = blockIdx.x * blockDim.x + threadIdx.x;
    if (i >= E) return;
    int d = g_dst[i];
    int pos = atomicAdd(&g_cursor[d], 1);
    g_csrc[pos] = g_src[i];
}

// ================= weight split =================
__global__ void wsplit_kernel(const float* __restrict__ w, __nv_bfloat16* __restrict__ hi,
                              __nv_bfloat16* __restrict__ lo, int n) {
    int i = blockIdx.x * blockDim.x + threadIdx.x;
    if (i >= n) return;
    __nv_bfloat16 h, l;
    split2(w[i], h, l);
    hi[i] = h;
    lo[i] = l;
}

// ================= layer-1: 16-dim gather =================
__global__ void gather16_kernel(const float* __restrict__ x, float* __restrict__ agg, int M) {
    int gt = blockIdx.x * blockDim.x + threadIdx.x;
    int n = gt >> 2;
    if (n >= M) return;
    int q = gt & 3;
    int rs0 = g_rowstart[n], rs1 = g_rowstart[n + 1];
    float4 acc = make_float4(0.f, 0.f, 0.f, 0.f);
    for (int i = rs0; i < rs1; i++) {
        int s0 = g_csrc[i];
        float4 v = __ldg(reinterpret_cast<const float4*>(x + (size_t)s0 * INDIM) + q);
        acc.x += v.x; acc.y += v.y; acc.z += v.z; acc.w += v.w;
    }
    float sc = 1.0f / (float)max(rs1 - rs0, 1);
    acc.x *= sc; acc.y *= sc; acc.z *= sc; acc.w *= sc;
    reinterpret_cast<float4*>(agg + (size_t)n * INDIM)[q] = acc;
}

// ================= layer-1 FFMA GEMM (K=32) =================
template <int S>
__global__ void __launch_bounds__(256)
sage_gemm_kernel(const float* __restrict__ A0, const float* __restrict__ A1,
                 const float* __restrict__ W0, const float* __restrict__ W1,
                 const float* __restrict__ bias, float* __restrict__ C, int M) {
    __shared__ float As[8][128];
    __shared__ float Bs[8][128];

    const int tid = threadIdx.x;
    const int m0 = blockIdx.x * 128;
    const int lm = tid >> 1;
    const int kq = (tid & 1) * 4;
    const int node = m0 + lm;
    const int tr = tid >> 4;
    const int tc = tid & 15;

    float acc[8][8];
#pragma unroll
    for (int i = 0; i < 8; i++)
#pragma unroll
        for (int j = 0; j < 8; j++) acc[i][j] = 0.f;

    const int K = 2 * S;
#pragma unroll 2
    for (int k0 = 0; k0 < K; k0 += 8) {
        const bool half = (k0 >= S);
        const float* Ab = half ? A1 : A0;
        const float* Wb = half ? W1 : W0;
        const int koff = (half ? k0 - S : k0) + kq;

        float4 va = make_float4(0.f, 0.f, 0.f, 0.f);
        if (node < M)
            va = *reinterpret_cast<const float4*>(Ab + (size_t)node * S + koff);
        float4 vb = *reinterpret_cast<const float4*>(Wb + (size_t)lm * S + koff);

        __syncthreads();
        As[kq + 0][lm] = va.x;
        As[kq + 1][lm] = va.y;
        As[kq + 2][lm] = va.z;
        As[kq + 3][lm] = va.w;
        Bs[kq + 0][lm] = vb.x;
        Bs[kq + 1][lm] = vb.y;
        Bs[kq + 2][lm] = vb.z;
        Bs[kq + 3][lm] = vb.w;
        __syncthreads();

#pragma unroll
        for (int k = 0; k < 8; k++) {
            float4 a0 = *reinterpret_cast<float4*>(&As[k][tr * 8]);
            float4 a1 = *reinterpret_cast<float4*>(&As[k][tr * 8 + 4]);
            float4 b0 = *reinterpret_cast<float4*>(&Bs[k][tc * 8]);
            float4 b1 = *reinterpret_cast<float4*>(&Bs[k][tc * 8 + 4]);
            float av[8] = {a0.x, a0.y, a0.z, a0.w, a1.x, a1.y, a1.z, a1.w};
            float bv[8] = {b0.x, b0.y, b0.z, b0.w, b1.x, b1.y, b1.z, b1.w};
#pragma unroll
            for (int i = 0; i < 8; i++)
#pragma unroll
                for (int j = 0; j < 8; j++) acc[i][j] += av[i] * bv[j];
        }
    }

    float4 bb0 = *reinterpret_cast<const float4*>(bias + tc * 8);
    float4 bb1 = *reinterpret_cast<const float4*>(bias + tc * 8 + 4);
    float bb[8] = {bb0.x, bb0.y, bb0.z, bb0.w, bb1.x, bb1.y, bb1.z, bb1.w};
#pragma unroll
    for (int i = 0; i < 8; i++) {
        int n = m0 + tr * 8 + i;
        if (n < M) {
            float4 o0, o1;
            o0.x = fmaxf(acc[i][0] + bb[0], 0.f);
            o0.y = fmaxf(acc[i][1] + bb[1], 0.f);
            o0.z = fmaxf(acc[i][2] + bb[2], 0.f);
            o0.w = fmaxf(acc[i][3] + bb[3], 0.f);
            o1.x = fmaxf(acc[i][4] + bb[4], 0.f);
            o1.y = fmaxf(acc[i][5] + bb[5], 0.f);
            o1.z = fmaxf(acc[i][6] + bb[6], 0.f);
            o1.w = fmaxf(acc[i][7] + bb[7], 0.f);
            *reinterpret_cast<float4*>(C + (size_t)n * HID + tc * 8) = o0;
            *reinterpret_cast<float4*>(C + (size_t)n * HID + tc * 8 + 4) = o1;
        }
    }
}

// ================= fused gather + tensor-core SAGE layer (layers 2/3) =================
// Per block: gather mean-agg for its 128 nodes directly into persistent bf16 hi/lo
// smem tiles, then C = relu(agg.W0^T + h.W1^T + bias). If FINAL, additionally
// computes out = C.Wh^T + bh in-block and skips storing C.
template <bool FINAL>
__global__ void __launch_bounds__(256)
fused_sage_kernel(const float* __restrict__ hIn,
                  const __nv_bfloat16* __restrict__ W0hi, const __nv_bfloat16* __restrict__ W0lo,
                  const __nv_bfloat16* __restrict__ W1hi, const __nv_bfloat16* __restrict__ W1lo,
                  const float* __restrict__ bias, float* __restrict__ C,
                  const float* __restrict__ Wh, const float* __restrict__ bh,
                  float* __restrict__ out, int M) {
    extern __shared__ char fsm[];
    __nv_bfloat16* sA0hi = reinterpret_cast<__nv_bfloat16*>(fsm + FOFF_A0HI);
    __nv_bfloat16* sA0lo = reinterpret_cast<__nv_bfloat16*>(fsm + FOFF_A0LO);
    __nv_bfloat16* sA1hi = reinterpret_cast<__nv_bfloat16*>(fsm + FOFF_A1HI);
    __nv_bfloat16* sA1lo = reinterpret_cast<__nv_bfloat16*>(fsm + FOFF_A1LO);
    __nv_bfloat16* sBhi  = reinterpret_cast<__nv_bfloat16*>(fsm + FOFF_BHI);
    __nv_bfloat16* sBlo  = reinterpret_cast<__nv_bfloat16*>(fsm + FOFF_BLO);
    float* sWh = reinterpret_cast<float*>(fsm + FOFF_WH);
    float* sbh = reinterpret_cast<float*>(fsm + FOFF_BH);

    const int tid = threadIdx.x;
    const int wid = tid >> 5;
    const int lane = tid & 31;
    const int wm = wid & 3;
    const int wn = wid >> 2;
    const int m0 = blockIdx.x * 128;

    if (FINAL) {
        for (int u = tid; u < OUTDIM * HID; u += 256) sWh[u] = Wh[u];
        if (tid < OUTDIM) sbh[tid] = bh[tid];
    }

    // ---- phase 1: fused CSR mean-gather into persistent full-K A0 hi/lo tiles ----
    {
        int rbase = wid * 16;
#pragma unroll 1
        for (int rr = 0; rr < 16; rr++) {
            int r = rbase + rr;
            int node = m0 + r;
            float4 a = make_float4(0.f, 0.f, 0.f, 0.f);
            if (node < M) {
                int rs0 = g_rowstart[node], rs1 = g_rowstart[node + 1];
                int i = rs0;
                for (; i + 2 <= rs1; i += 2) {
                    int s0 = g_csrc[i + 0];
                    int s1 = g_csrc[i + 1];
                    float4 v0 = __ldg(reinterpret_cast<const float4*>(hIn + (size_t)s0 * HID) + lane);
                    float4 v1 = __ldg(reinterpret_cast<const float4*>(hIn + (size_t)s1 * HID) + lane);
                    a.x += v0.x + v1.x;
                    a.y += v0.y + v1.y;
                    a.z += v0.z + v1.z;
                    a.w += v0.w + v1.w;
                }
                for (; i < rs1; i++) {
                    int s0 = g_csrc[i];
                    float4 v0 = __ldg(reinterpret_cast<const float4*>(hIn + (size_t)s0 * HID) + lane);
                    a.x += v0.x; a.y += v0.y; a.z += v0.z; a.w += v0.w;
                }
                float sc = 1.0f / (float)max(rs1 - rs0, 1);
                a.x *= sc; a.y *= sc; a.z *= sc; a.w *= sc;
            }
            __nv_bfloat16 h0, l0, h1, l1, h2, l2, h3, l3;
            split2(a.x, h0, l0);
            split2(a.y, h1, l1);
            split2(a.z, h2, l2);
            split2(a.w, h3, l3);
            uint2 ph, pl;
            ph.x = pack2(h0, h1); ph.y = pack2(h2, h3);
            pl.x = pack2(l0, l1); pl.y = pack2(l2, l3);
            *reinterpret_cast<uint2*>(sA0hi + r * A0STRIDE + lane * 4) = ph;
            *reinterpret_cast<uint2*>(sA0lo + r * A0STRIDE + lane * 4) = pl;
        }
    }
    __syncthreads();

    const uint32_t uA0hi = smem_u32(sA0hi);
    const uint32_t uA0lo = smem_u32(sA0lo);
    const uint32_t uA1hi = smem_u32(sA1hi);
    const uint32_t uA1lo = smem_u32(sA1lo);
    const uint32_t uBhi = smem_u32(sBhi);
    const uint32_t uBlo = smem_u32(sBlo);

    float acc[2][8][4];
#pragma unroll
    for (int i = 0; i < 2; i++)
#pragma unroll
        for (int j = 0; j < 8; j++)
#pragma unroll
            for (int k = 0; k < 4; k++) acc[i][j][k] = 0.f;

    const int arow = wm * 32 + (lane & 15);
    const int akof = (lane & 16) ? 8 : 0;
    const int nrow0 = wn * 64 + (lane & 7) + ((lane & 16) ? 8 : 0);
    const int nkof = (lane & 8) ? 8 : 0;

    // ---- phase 2: MMA mainloop, K = 2*128 in chunks of 32 ----
#pragma unroll
    for (int chunk = 0; chunk < 8; chunk++) {
        const bool selfp = (chunk >= 4);
        const __nv_bfloat16* WH = selfp ? W1hi : W0hi;
        const __nv_bfloat16* WL = selfp ? W1lo : W0lo;
        const int koff = (chunk & 3) * 32;

        __syncthreads();
        if (selfp) {
            // stage self-path A1 tile (fp32 -> hi/lo split)
#pragma unroll
            for (int i = 0; i < 4; i++) {
                int u = tid + i * 256;
                int row = u >> 3;
                int q = (u & 7) * 4;
                float4 v = make_float4(0.f, 0.f, 0.f, 0.f);
                int node = m0 + row;
                if (node < M)
                    v = *reinterpret_cast<const float4*>(hIn + (size_t)node * HID + koff + q);
                __nv_bfloat16 h0, l0, h1, l1, h2, l2, h3, l3;
                split2(v.x, h0, l0);
                split2(v.y, h1, l1);
                split2(v.z, h2, l2);
                split2(v.w, h3, l3);
                int so = row * TSTRIDE + q;
                uint2 ph, pl;
                ph.x = pack2(h0, h1); ph.y = pack2(h2, h3);
                pl.x = pack2(l0, l1); pl.y = pack2(l2, l3);
                *reinterpret_cast<uint2*>(sA1hi + so) = ph;
                *reinterpret_cast<uint2*>(sA1lo + so) = pl;
            }
        }
        // stage B tile
#pragma unroll
        for (int i = 0; i < 2; i++) {
            int u = tid + i * 256;
            int row = u >> 2;
            int c = (u & 3) * 8;
            uint4 vh = *reinterpret_cast<const uint4*>(WH + (size_t)row * HID + koff + c);
            uint4 vl = *reinterpret_cast<const uint4*>(WL + (size_t)row * HID + koff + c);
            int so = row * TSTRIDE + c;
            *reinterpret_cast<uint4*>(sBhi + so) = vh;
            *reinterpret_cast<uint4*>(sBlo + so) = vl;
        }
        __syncthreads();

#pragma unroll
        for (int ks = 0; ks < 2; ks++) {
            const int k0 = ks * 16;
            uint32_t ahi[2][4], alo[2][4];
#pragma unroll
            for (int mi = 0; mi < 2; mi++) {
                uint32_t off;
                if (!selfp)
                    off = uA0hi + ((arow + mi * 16) * A0STRIDE + koff + k0 + akof) * 2;
                else
                    off = uA1hi + ((arow + mi * 16) * TSTRIDE + k0 + akof) * 2;
                LDMX4(ahi[mi], off);
                uint32_t offl;
                if (!selfp)
                    offl = uA0lo + ((arow + mi * 16) * A0STRIDE + koff + k0 + akof) * 2;
                else
                    offl = uA1lo + ((arow + mi * 16) * TSTRIDE + k0 + akof) * 2;
                LDMX4(alo[mi], offl);
            }
#pragma unroll
            for (int np = 0; np < 4; np++) {
                uint32_t boff = ((nrow0 + np * 16) * TSTRIDE + k0 + nkof) * 2;
                uint32_t bh4[4], bl4[4];
                LDMX4(bh4, uBhi + boff);
                LDMX4(bl4, uBlo + boff);
#pragma unroll
                for (int mi = 0; mi < 2; mi++) {
#pragma unroll
                    for (int na = 0; na < 2; na++) {
                        float* c = acc[mi][np * 2 + na];
                        mma16816(c, ahi[mi], &bh4[na * 2]);
                        mma16816(c, ahi[mi], &bl4[na * 2]);
                        mma16816(c, alo[mi], &bh4[na * 2]);
                    }
                }
            }
        }
    }

    // ---- phase 3: epilogue ----
    if (!FINAL) {
#pragma unroll
        for (int mi = 0; mi < 2; mi++) {
            int row0 = m0 + wm * 32 + mi * 16 + (lane >> 2);
            int row1 = row0 + 8;
#pragma unroll
            for (int ni = 0; ni < 8; ni++) {
                int col = wn * 64 + ni * 8 + 2 * (lane & 3);
                float b0 = __ldg(bias + col);
                float b1 = __ldg(bias + col + 1);
                float* c = acc[mi][ni];
                if (row0 < M) {
                    float2 v;
                    v.x = fmaxf(c[0] + b0, 0.f);
                    v.y = fmaxf(c[1] + b1, 0.f);
                    *reinterpret_cast<float2*>(C + (size_t)row0 * HID + col) = v;
                }
                if (row1 < M) {
                    float2 v;
                    v.x = fmaxf(c[2] + b0, 0.f);
                    v.y = fmaxf(c[3] + b1, 0.f);
                    *reinterpret_cast<float2*>(C + (size_t)row1 * HID + col) = v;
                }
            }
        }
    } else {
        // fused final projection: out[row][j] = sum_col relu(acc+bias)*Wh[j][col] + bh[j]
        __syncthreads();   // all smem MMA reads done; safe to reuse red region
        float* red = reinterpret_cast<float*>(fsm + FOFF_RED);   // [128][4][2]
#pragma unroll
        for (int mi = 0; mi < 2; mi++) {
            float p0[OUTDIM] = {0.f, 0.f, 0.f, 0.f};
            float p1[OUTDIM] = {0.f, 0.f, 0.f, 0.f};
#pragma unroll
            for (int ni = 0; ni < 8; ni++) {
                int col = wn * 64 + ni * 8 + 2 * (lane & 3);
                float b0 = __ldg(bias + col);
                float b1 = __ldg(bias + col + 1);
                float* c = acc[mi][ni];
                float v0 = fmaxf(c[0] + b0, 0.f);
                float v1 = fmaxf(c[1] + b1, 0.f);
                float v2 = fmaxf(c[2] + b0, 0.f);
                float v3 = fmaxf(c[3] + b1, 0.f);
#pragma unroll
                for (int j = 0; j < OUTDIM; j++) {
                    float w0 = sWh[j * HID + col];
                    float w1 = sWh[j * HID + col + 1];
                    p0[j] += v0 * w0 + v1 * w1;
                    p1[j] += v2 * w0 + v3 * w1;
                }
            }
            // reduce across the 4 lanes of the quad (lane&3 = col groups)
#pragma unroll
            for (int j = 0; j < OUTDIM; j++) {
                p0[j] += __shfl_xor_sync(0xffffffffu, p0[j], 1);
                p0[j] += __shfl_xor_sync(0xffffffffu, p0[j], 2);
                p1[j] += __shfl_xor_sync(0xffffffffu, p1[j], 1);
                p1[j] += __shfl_xor_sync(0xffffffffu, p1[j], 2);
            }
            if ((lane & 3) == 0) {
                int r0 = wm * 32 + mi * 16 + (lane >> 2);
                int r1 = r0 + 8;
#pragma unroll
                for (int j = 0; j < OUTDIM; j++) {
                    red[r0 * 8 + j * 2 + wn] = p0[j];
                    red[r1 * 8 + j * 2 + wn] = p1[j];
                }
            }
        }
        __syncthreads();
        for (int u = tid; u < 128 * OUTDIM; u += 256) {
            int row = u >> 2;
            int j = u & 3;
            int node = m0 + row;
            if (node < M)
                out[(size_t)node * OUTDIM + j] = red[row * 8 + j * 2 + 0] + red[row * 8 + j * 2 + 1] + sbh[j];
        }
    }
}

// ---------------------------------------------------------------
extern "C" void kernel_launch(void* const* d_in, const int* in_sizes, int n_in,
                              void* d_out, int out_size) {
    (void)n_in; (void)out_size;
    const float* x   = (const float*)d_in[0];
    const int*   ei  = (const int*)d_in[1];
    const float* Wl1 = (const float*)d_in[2];
    const float* Wr1 = (const float*)d_in[3];
    const float* b1  = (const float*)d_in[4];
    const float* Wl2 = (const float*)d_in[5];
    const float* Wr2 = (const float*)d_in[6];
    const float* b2  = (const float*)d_in[7];
    const float* Wl3 = (const float*)d_in[8];
    const float* Wr3 = (const float*)d_in[9];
    const float* b3  = (const float*)d_in[10];
    const float* Wh  = (const float*)d_in[11];
    const float* bh  = (const float*)d_in[12];
    float* out = (float*)d_out;

    const int M = in_sizes[0] / INDIM;   // 50000
    const int E = in_sizes[1] / 2;       // 600000

    float *agg, *hA, *hB;
    int* deg;
    __nv_bfloat16 *wHi, *wLo;
    cudaGetSymbolAddress((void**)&agg, g_agg);
    cudaGetSymbolAddress((void**)&hA, g_hA);
    cudaGetSymbolAddress((void**)&hB, g_hB);
    cudaGetSymbolAddress((void**)&deg, g_deg);
    cudaGetSymbolAddress((void**)&wHi, g_wHi);
    cudaGetSymbolAddress((void**)&wLo, g_wLo);

    cudaFuncSetAttribute(fused_sage_kernel<false>,
                         cudaFuncAttributeMaxDynamicSharedMemorySize, FSM_TOTAL);
    cudaFuncSetAttribute(fused_sage_kernel<true>,
                         cudaFuncAttributeMaxDynamicSharedMemorySize, FSM_TOTAL);

    const int T = 256;
    const int NB = (M + SCAN_CHUNK - 1) / SCAN_CHUNK;

    // ---- CSR build ----
    detect_kernel<<<1, 64>>>(ei);
    zero_i_kernel<<<(M + T - 1) / T, T>>>(deg, M);
    convert_kernel<<<(E + T - 1) / T, T>>>(ei, E);
    scan_phase1<<<NB, 256>>>(M);
    scan_phase2<<<1, MAX_SCAN_BLOCKS>>>(NB);
    scan_phase3<<<NB, 256>>>(M, E);
    fill_kernel<<<(E + T - 1) / T, T>>>(E);

    // ---- weight splits ----
    const int WN = HID * HID;
    wsplit_kernel<<<(WN + T - 1) / T, T>>>(Wl2, wHi + 0 * WN, wLo + 0 * WN, WN);
    wsplit_kernel<<<(WN + T - 1) / T, T>>>(Wr2, wHi + 1 * WN, wLo + 1 * WN, WN);
    wsplit_kernel<<<(WN + T - 1) / T, T>>>(Wl3, wHi + 2 * WN, wLo + 2 * WN, WN);
    wsplit_kernel<<<(WN + T - 1) / T, T>>>(Wr3, wHi + 3 * WN, wLo + 3 * WN, WN);

    const int gemmBlocks = (M + 127) / 128;

    // ---- layer 1 (16 -> 128), FFMA ----
    gather16_kernel<<<((M * 4) + T - 1) / T, T>>>(x, agg, M);
    sage_gemm_kernel<INDIM><<<gemmBlocks, 256>>>(agg, x, Wl1, Wr1, b1, hA, M);

    // ---- layer 2 (128 -> 128), fused gather + mma ----
    fused_sage_kernel<false><<<gemmBlocks, 256, FSM_TOTAL>>>(
        hA, wHi + 0 * WN, wLo + 0 * WN, wHi + 1 * WN, wLo + 1 * WN,
        b2, hB, nullptr, nullptr, nullptr, M);

    // ---- layer 3 (128 -> 128) + final projection, fused ----
    fused_sage_kernel<true><<<gemmBlocks, 256, FSM_TOTAL>>>(
        hB, wHi + 2 * WN, wLo + 2 * WN, wHi + 3 * WN, wLo + 3 * WN,
        b3, nullptr, Wh, bh, out, M);
}

// round 9
// speedup vs baseline: 2.7662x; 1.9666x over previous
#include <cuda_runtime.h>
#include <cuda_bf16.h>
#include <cstdint>

#define NN 50000
#define HID 128
#define INDIM 16
#define OUTDIM 4
#define MAXE 600000
#define SCAN_CHUNK 1024
#define MAX_SCAN_BLOCKS 128
#define TSTRIDE 40   // smem tile row stride in bf16 elements (80B -> conflict-free ldmatrix)

// flat split-weight offsets (bf16 elems)
#define W2L_OFF 0
#define W2R_OFF 16384
#define W3L_OFF 32768
#define W3R_OFF 49152
#define W1L_OFF 65536
#define W1R_OFF 67584
#define WTOT    69632

// ---- scratch (static device globals; no runtime allocation) ----
__device__ float g_agg[NN * HID];
__device__ float g_hA[NN * HID];
__device__ float g_hB[NN * HID];
__device__ __nv_bfloat16 g_wHi[WTOT];
__device__ __nv_bfloat16 g_wLo[WTOT];
__device__ int   g_src[MAXE];
__device__ int   g_dst[MAXE];
__device__ int   g_csrc[MAXE];
__device__ int   g_deg[NN];
__device__ int   g_rowstart[NN + 1];
__device__ int   g_cursor[NN];
__device__ int   g_blocksum[MAX_SCAN_BLOCKS];
__device__ int   g_blockoff[MAX_SCAN_BLOCKS];
__device__ int   g_is64;

// ================= helpers =================
__device__ __forceinline__ uint32_t smem_u32(const void* p) {
    uint32_t a;
    asm("{ .reg .u64 t; cvta.to.shared.u64 t, %1; cvt.u32.u64 %0, t; }" : "=r"(a) : "l"(p));
    return a;
}

#define LDMX4(r, a)                                                            \
    asm volatile("ldmatrix.sync.aligned.m8n8.x4.shared.b16 {%0,%1,%2,%3}, [%4];" \
                 : "=r"((r)[0]), "=r"((r)[1]), "=r"((r)[2]), "=r"((r)[3])      \
                 : "r"(a))

__device__ __forceinline__ void mma16816(float* c, const uint32_t* a, const uint32_t* b) {
    asm volatile(
        "mma.sync.aligned.m16n8k16.row.col.f32.bf16.bf16.f32 "
        "{%0,%1,%2,%3}, {%4,%5,%6,%7}, {%8,%9}, {%0,%1,%2,%3};"
        : "+f"(c[0]), "+f"(c[1]), "+f"(c[2]), "+f"(c[3])
        : "r"(a[0]), "r"(a[1]), "r"(a[2]), "r"(a[3]), "r"(b[0]), "r"(b[1]));
}

__device__ __forceinline__ void split2(float v, __nv_bfloat16& hi, __nv_bfloat16& lo) {
    hi = __float2bfloat16(v);
    lo = __float2bfloat16(v - __bfloat162float(hi));
}
__device__ __forceinline__ uint32_t pack2(__nv_bfloat16 a, __nv_bfloat16 b) {
    __nv_bfloat162 t = __halves2bfloat162(a, b);
    return *reinterpret_cast<uint32_t*>(&t);
}

// ================= CSR build =================
__global__ void detect_kernel(const int* __restrict__ w) {
    __shared__ int anynz;
    if (threadIdx.x == 0) anynz = 0;
    __syncthreads();
    if (w[2 * threadIdx.x + 1] != 0) atomicOr(&anynz, 1);
    __syncthreads();
    if (threadIdx.x == 0) g_is64 = anynz ? 0 : 1;
}

__global__ void zero_i_kernel(int* __restrict__ p, int n) {
    int i = blockIdx.x * blockDim.x + threadIdx.x;
    if (i < n) p[i] = 0;
}

__global__ void convert_kernel(const int* __restrict__ w, int E) {
    int i = blockIdx.x * blockDim.x + threadIdx.x;
    if (i >= E) return;
    int s, d;
    if (g_is64) { s = w[2 * i]; d = w[2 * (E + i)]; }
    else        { s = w[i];     d = w[E + i];       }
    g_src[i] = s;
    g_dst[i] = d;
    atomicAdd(&g_deg[d], 1);
}

__device__ __forceinline__ void block_scan_1024(int& thread_sum, int& thread_excl, int* warp_buf) {
    int t = threadIdx.x;
    int lane = t & 31, w = t >> 5;
    int v = thread_sum;
#pragma unroll
    for (int off = 1; off < 32; off <<= 1) {
        int u = __shfl_up_sync(0xffffffffu, v, off);
        if (lane >= off) v += u;
    }
    if (lane == 31) warp_buf[w] = v;
    __syncthreads();
    if (w == 0) {
        int ws = (lane < 8) ? warp_buf[lane] : 0;
#pragma unroll
        for (int off = 1; off < 8; off <<= 1) {
            int u = __shfl_up_sync(0xffffffffu, ws, off);
            if (lane >= off) ws += u;
        }
        if (lane < 8) warp_buf[lane] = ws;
    }
    __syncthreads();
    thread_excl = v - thread_sum + (w > 0 ? warp_buf[w - 1] : 0);
}

__global__ void scan_phase1(int M) {
    __shared__ int warp_buf[8];
    int b = blockIdx.x, t = threadIdx.x;
    int base = b * SCAN_CHUNK + t * 4;
    int d[4] = {0, 0, 0, 0};
#pragma unroll
    for (int i = 0; i < 4; i++)
        if (base + i < M) d[i] = g_deg[base + i];
    int s = d[0] + d[1] + d[2] + d[3];
    int excl;
    block_scan_1024(s, excl, warp_buf);
    if (t == blockDim.x - 1) g_blocksum[b] = excl + s;
}

__global__ void scan_phase2(int NB) {
    __shared__ int buf[MAX_SCAN_BLOCKS];
    int t = threadIdx.x;
    if (t < NB) buf[t] = g_blocksum[t];
    __syncthreads();
    if (t == 0) {
        int run = 0;
        for (int i = 0; i < NB; i++) { int x = buf[i]; buf[i] = run; run += x; }
    }
    __syncthreads();
    if (t < NB) g_blockoff[t] = buf[t];
}

__global__ void scan_phase3(int M, int E) {
    __shared__ int warp_buf[8];
    int b = blockIdx.x, t = threadIdx.x;
    int base = b * SCAN_CHUNK + t * 4;
    int d[4] = {0, 0, 0, 0};
#pragma unroll
    for (int i = 0; i < 4; i++)
        if (base + i < M) d[i] = g_deg[base + i];
    int s = d[0] + d[1] + d[2] + d[3];
    int excl;
    block_scan_1024(s, excl, warp_buf);
    int run = excl + g_blockoff[b];
#pragma unroll
    for (int i = 0; i < 4; i++) {
        if (base + i < M) {
            g_rowstart[base + i] = run;
            g_cursor[base + i] = run;
            run += d[i];
        }
    }
    if (b == 0 && t == 0) g_rowstart[M] = E;
}

__global__ void fill_kernel(int E) {
    int i = blockIdx.x * blockDim.x + threadIdx.x;
    if (i >= E) return;
    int d = g_dst[i];
    int pos = atomicAdd(&g_cursor[d], 1);
    g_csrc[pos] = g_src[i];
}

// ================= combined weight split (all 6 matrices) =================
__global__ void wsplit_all_kernel(const float* __restrict__ Wl2, const float* __restrict__ Wr2,
                                  const float* __restrict__ Wl3, const float* __restrict__ Wr3,
                                  const float* __restrict__ Wl1, const float* __restrict__ Wr1) {
    int i = blockIdx.x * blockDim.x + threadIdx.x;
    if (i >= WTOT) return;
    const float* src;
    int off;
    if (i < W2R_OFF)      { src = Wl2; off = i - W2L_OFF; }
    else if (i < W3L_OFF) { src = Wr2; off = i - W2R_OFF; }
    else if (i < W3R_OFF) { src = Wl3; off = i - W3L_OFF; }
    else if (i < W1L_OFF) { src = Wr3; off = i - W3R_OFF; }
    else if (i < W1R_OFF) { src = Wl1; off = i - W1L_OFF; }
    else                  { src = Wr1; off = i - W1R_OFF; }
    __nv_bfloat16 h, l;
    split2(src[off], h, l);
    g_wHi[i] = h;
    g_wLo[i] = l;
}

// ================= gathers (fp32, CSR) =================
__global__ void gather128_kernel(const float* __restrict__ h, float* __restrict__ agg, int M) {
    int gt = blockIdx.x * blockDim.x + threadIdx.x;
    int n = gt >> 5;
    if (n >= M) return;
    int lane = gt & 31;
    int rs0 = g_rowstart[n], rs1 = g_rowstart[n + 1];
    float4 acc = make_float4(0.f, 0.f, 0.f, 0.f);
    int i = rs0;
    for (; i + 4 <= rs1; i += 4) {
        int s0 = g_csrc[i + 0];
        int s1 = g_csrc[i + 1];
        int s2 = g_csrc[i + 2];
        int s3 = g_csrc[i + 3];
        float4 v0 = __ldg(reinterpret_cast<const float4*>(h + (size_t)s0 * HID) + lane);
        float4 v1 = __ldg(reinterpret_cast<const float4*>(h + (size_t)s1 * HID) + lane);
        float4 v2 = __ldg(reinterpret_cast<const float4*>(h + (size_t)s2 * HID) + lane);
        float4 v3 = __ldg(reinterpret_cast<const float4*>(h + (size_t)s3 * HID) + lane);
        acc.x += v0.x + v1.x + v2.x + v3.x;
        acc.y += v0.y + v1.y + v2.y + v3.y;
        acc.z += v0.z + v1.z + v2.z + v3.z;
        acc.w += v0.w + v1.w + v2.w + v3.w;
    }
    for (; i < rs1; i++) {
        int s0 = g_csrc[i];
        float4 v0 = __ldg(reinterpret_cast<const float4*>(h + (size_t)s0 * HID) + lane);
        acc.x += v0.x; acc.y += v0.y; acc.z += v0.z; acc.w += v0.w;
    }
    float sc = 1.0f / (float)max(rs1 - rs0, 1);
    acc.x *= sc; acc.y *= sc; acc.z *= sc; acc.w *= sc;
    reinterpret_cast<float4*>(agg + (size_t)n * HID)[lane] = acc;
}

__global__ void gather16_kernel(const float* __restrict__ x, float* __restrict__ agg, int M) {
    int gt = blockIdx.x * blockDim.x + threadIdx.x;
    int n = gt >> 2;
    if (n >= M) return;
    int q = gt & 3;
    int rs0 = g_rowstart[n], rs1 = g_rowstart[n + 1];
    float4 acc = make_float4(0.f, 0.f, 0.f, 0.f);
    for (int i = rs0; i < rs1; i++) {
        int s0 = g_csrc[i];
        float4 v = __ldg(reinterpret_cast<const float4*>(x + (size_t)s0 * INDIM) + q);
        acc.x += v.x; acc.y += v.y; acc.z += v.z; acc.w += v.w;
    }
    float sc = 1.0f / (float)max(rs1 - rs0, 1);
    acc.x *= sc; acc.y *= sc; acc.z *= sc; acc.w *= sc;
    reinterpret_cast<float4*>(agg + (size_t)n * INDIM)[q] = acc;
}

// ================= layer-1 tensor GEMM (K=32) via mma.sync =================
// C[n][j] = relu( agg[n,0:16].Wl1[j,:] + x[n,0:16].Wr1[j,:] + b1[j] )
__global__ void __launch_bounds__(256)
tensor_l1_kernel(const float* __restrict__ agg, const float* __restrict__ x,
                 const __nv_bfloat16* __restrict__ WHi, const __nv_bfloat16* __restrict__ WLo,
                 const float* __restrict__ bias, float* __restrict__ C, int M) {
    __shared__ __nv_bfloat16 sAhi[128 * TSTRIDE];
    __shared__ __nv_bfloat16 sAlo[128 * TSTRIDE];
    __shared__ __nv_bfloat16 sBhi[128 * TSTRIDE];
    __shared__ __nv_bfloat16 sBlo[128 * TSTRIDE];

    const int tid = threadIdx.x;
    const int wid = tid >> 5;
    const int lane = tid & 31;
    const int wm = wid & 3;
    const int wn = wid >> 2;
    const int m0 = blockIdx.x * 128;

    // ---- stage A: [agg | x] 128 x 32 (fp32 -> bf16 hi/lo) ----
    {
        int row = tid >> 1;
        int half = tid & 1;                 // 0 = agg cols 0-15, 1 = x cols 16-31
        const float* src = half ? x : agg;
        int node = m0 + row;
        float4 v[4];
#pragma unroll
        for (int i = 0; i < 4; i++) v[i] = make_float4(0.f, 0.f, 0.f, 0.f);
        if (node < M) {
            const float4* p = reinterpret_cast<const float4*>(src + (size_t)node * INDIM);
#pragma unroll
            for (int i = 0; i < 4; i++) v[i] = p[i];
        }
        int so = row * TSTRIDE + half * 16;
#pragma unroll
        for (int i = 0; i < 4; i++) {
            __nv_bfloat16 h0, l0, h1, l1, h2, l2, h3, l3;
            split2(v[i].x, h0, l0);
            split2(v[i].y, h1, l1);
            split2(v[i].z, h2, l2);
            split2(v[i].w, h3, l3);
            uint2 ph, pl;
            ph.x = pack2(h0, h1); ph.y = pack2(h2, h3);
            pl.x = pack2(l0, l1); pl.y = pack2(l2, l3);
            *reinterpret_cast<uint2*>(sAhi + so + i * 4) = ph;
            *reinterpret_cast<uint2*>(sAlo + so + i * 4) = pl;
        }
    }
    // ---- stage B: [Wl1 | Wr1] 128 x 32 (pre-split bf16) ----
    {
        int row = tid >> 1;
        int half = tid & 1;                 // 0 = Wl1 (offset 0), 1 = Wr1 (offset 2048)
        const __nv_bfloat16* WH = WHi + half * 2048;
        const __nv_bfloat16* WL = WLo + half * 2048;
        int so = row * TSTRIDE + half * 16;
        uint4 h0 = *reinterpret_cast<const uint4*>(WH + row * 16);
        uint4 h1 = *reinterpret_cast<const uint4*>(WH + row * 16 + 8);
        uint4 l0 = *reinterpret_cast<const uint4*>(WL + row * 16);
        uint4 l1 = *reinterpret_cast<const uint4*>(WL + row * 16 + 8);
        *reinterpret_cast<uint4*>(sBhi + so) = h0;
        *reinterpret_cast<uint4*>(sBhi + so + 8) = h1;
        *reinterpret_cast<uint4*>(sBlo + so) = l0;
        *reinterpret_cast<uint4*>(sBlo + so + 8) = l1;
    }
    __syncthreads();

    const uint32_t uAhi = smem_u32(sAhi);
    const uint32_t uAlo = smem_u32(sAlo);
    const uint32_t uBhi = smem_u32(sBhi);
    const uint32_t uBlo = smem_u32(sBlo);

    float acc[2][8][4];
#pragma unroll
    for (int i = 0; i < 2; i++)
#pragma unroll
        for (int j = 0; j < 8; j++)
#pragma unroll
            for (int k = 0; k < 4; k++) acc[i][j][k] = 0.f;

    const int arow = wm * 32 + (lane & 15);
    const int akof = (lane & 16) ? 8 : 0;
    const int nrow0 = wn * 64 + (lane & 7) + ((lane & 16) ? 8 : 0);
    const int nkof = (lane & 8) ? 8 : 0;

#pragma unroll
    for (int ks = 0; ks < 2; ks++) {
        const int k0 = ks * 16;
        uint32_t ahi[2][4], alo[2][4];
#pragma unroll
        for (int mi = 0; mi < 2; mi++) {
            uint32_t off = ((arow + mi * 16) * TSTRIDE + k0 + akof) * 2;
            LDMX4(ahi[mi], uAhi + off);
            LDMX4(alo[mi], uAlo + off);
        }
#pragma unroll
        for (int np = 0; np < 4; np++) {
            uint32_t boff = ((nrow0 + np * 16) * TSTRIDE + k0 + nkof) * 2;
            uint32_t bh4[4], bl4[4];
            LDMX4(bh4, uBhi + boff);
            LDMX4(bl4, uBlo + boff);
#pragma unroll
            for (int mi = 0; mi < 2; mi++) {
#pragma unroll
                for (int na = 0; na < 2; na++) {
                    float* c = acc[mi][np * 2 + na];
                    mma16816(c, ahi[mi], &bh4[na * 2]);
                    mma16816(c, ahi[mi], &bl4[na * 2]);
                    mma16816(c, alo[mi], &bh4[na * 2]);
                }
            }
        }
    }

#pragma unroll
    for (int mi = 0; mi < 2; mi++) {
        int row0 = m0 + wm * 32 + mi * 16 + (lane >> 2);
        int row1 = row0 + 8;
#pragma unroll
        for (int ni = 0; ni < 8; ni++) {
            int col = wn * 64 + ni * 8 + 2 * (lane & 3);
            float b0 = __ldg(bias + col);
            float b1 = __ldg(bias + col + 1);
            float* c = acc[mi][ni];
            if (row0 < M) {
                float2 v;
                v.x = fmaxf(c[0] + b0, 0.f);
                v.y = fmaxf(c[1] + b1, 0.f);
                *reinterpret_cast<float2*>(C + (size_t)row0 * HID + col) = v;
            }
            if (row1 < M) {
                float2 v;
                v.x = fmaxf(c[2] + b0, 0.f);
                v.y = fmaxf(c[3] + b1, 0.f);
                *reinterpret_cast<float2*>(C + (size_t)row1 * HID + col) = v;
            }
        }
    }
}

// ================= tensor-core SAGE GEMM (layers 2/3) via mma.sync =================
// C[n][j] = relu( agg[n,:].W0[j,:] + h[n,:].W1[j,:] + bias[j] ),  K = 2*128.
// FINAL: additionally out = C.Wh^T + bh, and C is not stored.
template <bool FINAL>
__global__ void __launch_bounds__(256)
tensor_sage_kernel(const float* __restrict__ A0, const float* __restrict__ A1,
                   const __nv_bfloat16* __restrict__ W0hi, const __nv_bfloat16* __restrict__ W0lo,
                   const __nv_bfloat16* __restrict__ W1hi, const __nv_bfloat16* __restrict__ W1lo,
                   const float* __restrict__ bias, float* __restrict__ C,
                   const float* __restrict__ Wh, const float* __restrict__ bh,
                   float* __restrict__ out, int M) {
    __shared__ __nv_bfloat16 sAhi[128 * TSTRIDE];
    __shared__ __nv_bfloat16 sAlo[128 * TSTRIDE];
    __shared__ __nv_bfloat16 sBhi[128 * TSTRIDE];
    __shared__ __nv_bfloat16 sBlo[128 * TSTRIDE];
    __shared__ float sWh[OUTDIM * HID];
    __shared__ float sbh[OUTDIM];
    __shared__ float red[128 * 8];

    const int tid = threadIdx.x;
    const int wid = tid >> 5;
    const int lane = tid & 31;
    const int wm = wid & 3;      // warp row tile: rows wm*32 .. +31
    const int wn = wid >> 2;     // warp col tile: cols wn*64 .. +63
    const int m0 = blockIdx.x * 128;

    if (FINAL) {
        for (int u = tid; u < OUTDIM * HID; u += 256) sWh[u] = Wh[u];
        if (tid < OUTDIM) sbh[tid] = bh[tid];
    }

    const uint32_t uAhi = smem_u32(sAhi);
    const uint32_t uAlo = smem_u32(sAlo);
    const uint32_t uBhi = smem_u32(sBhi);
    const uint32_t uBlo = smem_u32(sBlo);

    float acc[2][8][4];
#pragma unroll
    for (int i = 0; i < 2; i++)
#pragma unroll
        for (int j = 0; j < 8; j++)
#pragma unroll
            for (int k = 0; k < 4; k++) acc[i][j][k] = 0.f;

    const int arow = wm * 32 + (lane & 15);
    const int akof = (lane & 16) ? 8 : 0;
    const int nrow0 = wn * 64 + (lane & 7) + ((lane & 16) ? 8 : 0);
    const int nkof = (lane & 8) ? 8 : 0;

#pragma unroll
    for (int chunk = 0; chunk < 8; chunk++) {
        const float* A = (chunk < 4) ? A0 : A1;
        const __nv_bfloat16* WH = (chunk < 4) ? W0hi : W1hi;
        const __nv_bfloat16* WL = (chunk < 4) ? W0lo : W1lo;
        const int koff = (chunk & 3) * 32;

        __syncthreads();
        // ---- load A (fp32 -> split bf16 hi/lo into smem), 128 rows x 32 k ----
#pragma unroll
        for (int i = 0; i < 4; i++) {
            int u = tid + i * 256;            // 1024 float4 units
            int row = u >> 3;
            int q = (u & 7) * 4;
            float4 v = make_float4(0.f, 0.f, 0.f, 0.f);
            int node = m0 + row;
            if (node < M)
                v = *reinterpret_cast<const float4*>(A + (size_t)node * HID + koff + q);
            __nv_bfloat16 h0, l0, h1, l1, h2, l2, h3, l3;
            split2(v.x, h0, l0);
            split2(v.y, h1, l1);
            split2(v.z, h2, l2);
            split2(v.w, h3, l3);
            int so = row * TSTRIDE + q;
            uint2 ph, pl;
            ph.x = pack2(h0, h1); ph.y = pack2(h2, h3);
            pl.x = pack2(l0, l1); pl.y = pack2(l2, l3);
            *reinterpret_cast<uint2*>(sAhi + so) = ph;
            *reinterpret_cast<uint2*>(sAlo + so) = pl;
        }
        // ---- load B (bf16 hi/lo), 128 rows x 32 k ----
#pragma unroll
        for (int i = 0; i < 2; i++) {
            int u = tid + i * 256;            // 512 uint4 units
            int row = u >> 2;
            int c = (u & 3) * 8;
            uint4 vh = *reinterpret_cast<const uint4*>(WH + (size_t)row * HID + koff + c);
            uint4 vl = *reinterpret_cast<const uint4*>(WL + (size_t)row * HID + koff + c);
            int so = row * TSTRIDE + c;
            *reinterpret_cast<uint4*>(sBhi + so) = vh;
            *reinterpret_cast<uint4*>(sBlo + so) = vl;
        }
        __syncthreads();

        // ---- 2 k-steps of 16 ----
#pragma unroll
        for (int ks = 0; ks < 2; ks++) {
            const int k0 = ks * 16;
            uint32_t ahi[2][4], alo[2][4];
#pragma unroll
            for (int mi = 0; mi < 2; mi++) {
                uint32_t off = ((arow + mi * 16) * TSTRIDE + k0 + akof) * 2;
                LDMX4(ahi[mi], uAhi + off);
                LDMX4(alo[mi], uAlo + off);
            }
#pragma unroll
            for (int np = 0; np < 4; np++) {
                uint32_t boff = ((nrow0 + np * 16) * TSTRIDE + k0 + nkof) * 2;
                uint32_t bh4[4], bl4[4];
                LDMX4(bh4, uBhi + boff);
                LDMX4(bl4, uBlo + boff);
#pragma unroll
                for (int mi = 0; mi < 2; mi++) {
#pragma unroll
                    for (int na = 0; na < 2; na++) {
                        float* c = acc[mi][np * 2 + na];
                        mma16816(c, ahi[mi], &bh4[na * 2]);
                        mma16816(c, ahi[mi], &bl4[na * 2]);
                        mma16816(c, alo[mi], &bh4[na * 2]);
                    }
                }
            }
        }
    }

    if (!FINAL) {
        // ---- epilogue: bias + relu, fp32 stores ----
#pragma unroll
        for (int mi = 0; mi < 2; mi++) {
            int row0 = m0 + wm * 32 + mi * 16 + (lane >> 2);
            int row1 = row0 + 8;
#pragma unroll
            for (int ni = 0; ni < 8; ni++) {
                int col = wn * 64 + ni * 8 + 2 * (lane & 3);
                float b0 = __ldg(bias + col);
                float b1 = __ldg(bias + col + 1);
                float* c = acc[mi][ni];
                if (row0 < M) {
                    float2 v;
                    v.x = fmaxf(c[0] + b0, 0.f);
                    v.y = fmaxf(c[1] + b1, 0.f);
                    *reinterpret_cast<float2*>(C + (size_t)row0 * HID + col) = v;
                }
                if (row1 < M) {
                    float2 v;
                    v.x = fmaxf(c[2] + b0, 0.f);
                    v.y = fmaxf(c[3] + b1, 0.f);
                    *reinterpret_cast<float2*>(C + (size_t)row1 * HID + col) = v;
                }
            }
        }
    } else {
        // ---- fused final projection: out = relu(acc+bias).Wh^T + bh ----
#pragma unroll
        for (int mi = 0; mi < 2; mi++) {
            float p0[OUTDIM] = {0.f, 0.f, 0.f, 0.f};
            float p1[OUTDIM] = {0.f, 0.f, 0.f, 0.f};
#pragma unroll
            for (int ni = 0; ni < 8; ni++) {
                int col = wn * 64 + ni * 8 + 2 * (lane & 3);
                float b0 = __ldg(bias + col);
                float b1 = __ldg(bias + col + 1);
                float* c = acc[mi][ni];
                float v0 = fmaxf(c[0] + b0, 0.f);
                float v1 = fmaxf(c[1] + b1, 0.f);
                float v2 = fmaxf(c[2] + b0, 0.f);
                float v3 = fmaxf(c[3] + b1, 0.f);
#pragma unroll
                for (int j = 0; j < OUTDIM; j++) {
                    float w0 = sWh[j * HID + col];
                    float w1 = sWh[j * HID + col + 1];
                    p0[j] += v0 * w0 + v1 * w1;
                    p1[j] += v2 * w0 + v3 * w1;
                }
            }
#pragma unroll
            for (int j = 0; j < OUTDIM; j++) {
                p0[j] += __shfl_xor_sync(0xffffffffu, p0[j], 1);
                p0[j] += __shfl_xor_sync(0xffffffffu, p0[j], 2);
                p1[j] += __shfl_xor_sync(0xffffffffu, p1[j], 1);
                p1[j] += __shfl_xor_sync(0xffffffffu, p1[j], 2);
            }
            if ((lane & 3) == 0) {
                int r0 = wm * 32 + mi * 16 + (lane >> 2);
                int r1 = r0 + 8;
#pragma unroll
                for (int j = 0; j < OUTDIM; j++) {
                    red[r0 * 8 + j * 2 + wn] = p0[j];
                    red[r1 * 8 + j * 2 + wn] = p1[j];
                }
            }
        }
        __syncthreads();
        for (int u = tid; u < 128 * OUTDIM; u += 256) {
            int row = u >> 2;
            int j = u & 3;
            int node = m0 + row;
            if (node < M)
                out[(size_t)node * OUTDIM + j] =
                    red[row * 8 + j * 2 + 0] + red[row * 8 + j * 2 + 1] + sbh[j];
        }
    }
}

// ---------------------------------------------------------------
extern "C" void kernel_launch(void* const* d_in, const int* in_sizes, int n_in,
                              void* d_out, int out_size) {
    (void)n_in; (void)out_size;
    const float* x   = (const float*)d_in[0];
    const int*   ei  = (const int*)d_in[1];
    const float* Wl1 = (const float*)d_in[2];
    const float* Wr1 = (const float*)d_in[3];
    const float* b1  = (const float*)d_in[4];
    const float* Wl2 = (const float*)d_in[5];
    const float* Wr2 = (const float*)d_in[6];
    const float* b2  = (const float*)d_in[7];
    const float* Wl3 = (const float*)d_in[8];
    const float* Wr3 = (const float*)d_in[9];
    const float* b3  = (const float*)d_in[10];
    const float* Wh  = (const float*)d_in[11];
    const float* bh  = (const float*)d_in[12];
    float* out = (float*)d_out;

    const int M = in_sizes[0] / INDIM;   // 50000
    const int E = in_sizes[1] / 2;       // 600000

    float *agg, *hA, *hB;
    int* deg;
    __nv_bfloat16 *wHi, *wLo;
    cudaGetSymbolAddress((void**)&agg, g_agg);
    cudaGetSymbolAddress((void**)&hA, g_hA);
    cudaGetSymbolAddress((void**)&hB, g_hB);
    cudaGetSymbolAddress((void**)&deg, g_deg);
    cudaGetSymbolAddress((void**)&wHi, g_wHi);
    cudaGetSymbolAddress((void**)&wLo, g_wLo);

    const int T = 256;
    const int NB = (M + SCAN_CHUNK - 1) / SCAN_CHUNK;

    // ---- CSR build ----
    detect_kernel<<<1, 64>>>(ei);
    zero_i_kernel<<<(M + T - 1) / T, T>>>(deg, M);
    convert_kernel<<<(E + T - 1) / T, T>>>(ei, E);
    scan_phase1<<<NB, 256>>>(M);
    scan_phase2<<<1, MAX_SCAN_BLOCKS>>>(NB);
    scan_phase3<<<NB, 256>>>(M, E);
    fill_kernel<<<(E + T - 1) / T, T>>>(E);

    // ---- weight splits (all 6 in one launch) ----
    wsplit_all_kernel<<<(WTOT + T - 1) / T, T>>>(Wl2, Wr2, Wl3, Wr3, Wl1, Wr1);

    const int gemmBlocks = (M + 127) / 128;

    // ---- layer 1 (16 -> 128), mma.sync ----
    gather16_kernel<<<((M * 4) + T - 1) / T, T>>>(x, agg, M);
    tensor_l1_kernel<<<gemmBlocks, 256>>>(agg, x, wHi + W1L_OFF, wLo + W1L_OFF, b1, hA, M);

    // ---- layer 2 (128 -> 128), mma.sync ----
    gather128_kernel<<<((M * 32) + T - 1) / T, T>>>(hA, agg, M);
    tensor_sage_kernel<false><<<gemmBlocks, 256>>>(agg, hA,
        wHi + W2L_OFF, wLo + W2L_OFF, wHi + W2R_OFF, wLo + W2R_OFF,
        b2, hB, nullptr, nullptr, nullptr, M);

    // ---- layer 3 (128 -> 128) + fused final projection ----
    gather128_kernel<<<((M * 32) + T - 1) / T, T>>>(hB, agg, M);
    tensor_sage_kernel<true><<<gemmBlocks, 256>>>(agg, hB,
        wHi + W3L_OFF, wLo + W3L_OFF, wHi + W3R_OFF, wLo + W3R_OFF,
        b3, nullptr, Wh, bh, out, M);
}

// round 10
// speedup vs baseline: 2.7781x; 1.0043x over previous
#include <cuda_runtime.h>
#include <cuda_bf16.h>
#include <cuda_fp16.h>
#include <cstdint>

#define NN 50000
#define HID 128
#define INDIM 16
#define OUTDIM 4
#define MAXE 600000
#define SCAN_CHUNK 1024
#define MAX_SCAN_BLOCKS 128
#define TSTRIDE 40   // smem tile row stride in bf16 elements (80B -> conflict-free ldmatrix)

// flat split-weight offsets (bf16 elems)
#define W2L_OFF 0
#define W2R_OFF 16384
#define W3L_OFF 32768
#define W3R_OFF 49152
#define W1L_OFF 65536
#define W1R_OFF 67584
#define WTOT    69632

// ---- scratch (static device globals; no runtime allocation) ----
__device__ float g_agg[NN * HID];
__device__ float g_hA[NN * HID];
__device__ float g_hB[NN * HID];
__device__ __half g_hA16[NN * HID];
__device__ __half g_hB16[NN * HID];
__device__ __nv_bfloat16 g_wHi[WTOT];
__device__ __nv_bfloat16 g_wLo[WTOT];
__device__ int   g_src[MAXE];
__device__ int   g_dst[MAXE];
__device__ int   g_csrc[MAXE];
__device__ int   g_deg[NN];
__device__ int   g_rowstart[NN + 1];
__device__ int   g_cursor[NN];
__device__ int   g_blocksum[MAX_SCAN_BLOCKS];
__device__ int   g_is64;

// ================= helpers =================
__device__ __forceinline__ uint32_t smem_u32(const void* p) {
    uint32_t a;
    asm("{ .reg .u64 t; cvta.to.shared.u64 t, %1; cvt.u32.u64 %0, t; }" : "=r"(a) : "l"(p));
    return a;
}

#define LDMX4(r, a)                                                            \
    asm volatile("ldmatrix.sync.aligned.m8n8.x4.shared.b16 {%0,%1,%2,%3}, [%4];" \
                 : "=r"((r)[0]), "=r"((r)[1]), "=r"((r)[2]), "=r"((r)[3])      \
                 : "r"(a))

__device__ __forceinline__ void mma16816(float* c, const uint32_t* a, const uint32_t* b) {
    asm volatile(
        "mma.sync.aligned.m16n8k16.row.col.f32.bf16.bf16.f32 "
        "{%0,%1,%2,%3}, {%4,%5,%6,%7}, {%8,%9}, {%0,%1,%2,%3};"
        : "+f"(c[0]), "+f"(c[1]), "+f"(c[2]), "+f"(c[3])
        : "r"(a[0]), "r"(a[1]), "r"(a[2]), "r"(a[3]), "r"(b[0]), "r"(b[1]));
}

__device__ __forceinline__ void split2(float v, __nv_bfloat16& hi, __nv_bfloat16& lo) {
    hi = __float2bfloat16(v);
    lo = __float2bfloat16(v - __bfloat162float(hi));
}
__device__ __forceinline__ uint32_t pack2(__nv_bfloat16 a, __nv_bfloat16 b) {
    __nv_bfloat162 t = __halves2bfloat162(a, b);
    return *reinterpret_cast<uint32_t*>(&t);
}

// ================= CSR build =================
// init: zero degrees; block 0 additionally detects int64-vs-int32 edge dtype
// (int64 edge ids < 2^31 have all-zero hi words at odd 32-bit positions).
__global__ void init_kernel(const int* __restrict__ w, int M) {
    int i = blockIdx.x * blockDim.x + threadIdx.x;
    if (i < M) g_deg[i] = 0;
    if (blockIdx.x == 0) {
        __shared__ int anynz;
        if (threadIdx.x == 0) anynz = 0;
        __syncthreads();
        if (threadIdx.x < 64 && w[2 * threadIdx.x + 1] != 0) atomicOr(&anynz, 1);
        __syncthreads();
        if (threadIdx.x == 0) g_is64 = anynz ? 0 : 1;
    }
}

__global__ void convert_kernel(const int* __restrict__ w, int E) {
    int i = blockIdx.x * blockDim.x + threadIdx.x;
    if (i >= E) return;
    int s, d;
    if (g_is64) { s = w[2 * i]; d = w[2 * (E + i)]; }
    else        { s = w[i];     d = w[E + i];       }
    g_src[i] = s;
    g_dst[i] = d;
    atomicAdd(&g_deg[d], 1);
}

__device__ __forceinline__ void block_scan_1024(int& thread_sum, int& thread_excl, int* warp_buf) {
    int t = threadIdx.x;
    int lane = t & 31, w = t >> 5;
    int v = thread_sum;
#pragma unroll
    for (int off = 1; off < 32; off <<= 1) {
        int u = __shfl_up_sync(0xffffffffu, v, off);
        if (lane >= off) v += u;
    }
    if (lane == 31) warp_buf[w] = v;
    __syncthreads();
    if (w == 0) {
        int ws = (lane < 8) ? warp_buf[lane] : 0;
#pragma unroll
        for (int off = 1; off < 8; off <<= 1) {
            int u = __shfl_up_sync(0xffffffffu, ws, off);
            if (lane >= off) ws += u;
        }
        if (lane < 8) warp_buf[lane] = ws;
    }
    __syncthreads();
    thread_excl = v - thread_sum + (w > 0 ? warp_buf[w - 1] : 0);
}

__global__ void scan_phase1(int M) {
    __shared__ int warp_buf[8];
    int b = blockIdx.x, t = threadIdx.x;
    int base = b * SCAN_CHUNK + t * 4;
    int d[4] = {0, 0, 0, 0};
#pragma unroll
    for (int i = 0; i < 4; i++)
        if (base + i < M) d[i] = g_deg[base + i];
    int s = d[0] + d[1] + d[2] + d[3];
    int excl;
    block_scan_1024(s, excl, warp_buf);
    if (t == blockDim.x - 1) g_blocksum[b] = excl + s;
}

// phase2 folded in: each block computes its own offset from g_blocksum.
__global__ void scan_phase3(int M, int E, int NB) {
    __shared__ int warp_buf[8];
    __shared__ int bsum[MAX_SCAN_BLOCKS];
    __shared__ int boff;
    int b = blockIdx.x, t = threadIdx.x;
    if (t < NB) bsum[t] = g_blocksum[t];
    __syncthreads();
    if (t == 0) {
        int run = 0;
        for (int i = 0; i < b; i++) run += bsum[i];
        boff = run;
    }
    int base = b * SCAN_CHUNK + t * 4;
    int d[4] = {0, 0, 0, 0};
#pragma unroll
    for (int i = 0; i < 4; i++)
        if (base + i < M) d[i] = g_deg[base + i];
    int s = d[0] + d[1] + d[2] + d[3];
    int excl;
    block_scan_1024(s, excl, warp_buf);
    __syncthreads();
    int run = excl + boff;
#pragma unroll
    for (int i = 0; i < 4; i++) {
        if (base + i < M) {
            g_rowstart[base + i] = run;
            g_cursor[base + i] = run;
            run += d[i];
        }
    }
    if (b == 0 && t == 0) g_rowstart[M] = E;
}

__global__ void fill_kernel(int E) {
    int i = blockIdx.x * blockDim.x + threadIdx.x;
    if (i >= E) return;
    int d = g_dst[i];
    int pos = atomicAdd(&g_cursor[d], 1);
    g_csrc[pos] = g_src[i];
}

// ================= combined weight split (all 6 matrices) =================
__global__ void wsplit_all_kernel(const float* __restrict__ Wl2, const float* __restrict__ Wr2,
                                  const float* __restrict__ Wl3, const float* __restrict__ Wr3,
                                  const float* __restrict__ Wl1, const float* __restrict__ Wr1) {
    int i = blockIdx.x * blockDim.x + threadIdx.x;
    if (i >= WTOT) return;
    const float* src;
    int off;
    if (i < W2R_OFF)      { src = Wl2; off = i - W2L_OFF; }
    else if (i < W3L_OFF) { src = Wr2; off = i - W2R_OFF; }
    else if (i < W3R_OFF) { src = Wl3; off = i - W3L_OFF; }
    else if (i < W1L_OFF) { src = Wr3; off = i - W3R_OFF; }
    else if (i < W1R_OFF) { src = Wl1; off = i - W1L_OFF; }
    else                  { src = Wr1; off = i - W1R_OFF; }
    __nv_bfloat16 h, l;
    split2(src[off], h, l);
    g_wHi[i] = h;
    g_wLo[i] = l;
}

// ================= gathers (CSR) =================
// 128-dim mean-gather over fp16 mirror of h. One warp/node, lane = 4 cols (8B).
__global__ void gather128_f16(const __half* __restrict__ h16, float* __restrict__ agg, int M) {
    int gt = blockIdx.x * blockDim.x + threadIdx.x;
    int n = gt >> 5;
    if (n >= M) return;
    int lane = gt & 31;
    int rs0 = g_rowstart[n], rs1 = g_rowstart[n + 1];
    float4 acc = make_float4(0.f, 0.f, 0.f, 0.f);
    int i = rs0;
    for (; i + 4 <= rs1; i += 4) {
        int s0 = g_csrc[i + 0];
        int s1 = g_csrc[i + 1];
        int s2 = g_csrc[i + 2];
        int s3 = g_csrc[i + 3];
        uint2 r0 = __ldg(reinterpret_cast<const uint2*>(h16 + (size_t)s0 * HID) + lane);
        uint2 r1 = __ldg(reinterpret_cast<const uint2*>(h16 + (size_t)s1 * HID) + lane);
        uint2 r2 = __ldg(reinterpret_cast<const uint2*>(h16 + (size_t)s2 * HID) + lane);
        uint2 r3 = __ldg(reinterpret_cast<const uint2*>(h16 + (size_t)s3 * HID) + lane);
        float2 a0 = __half22float2(*reinterpret_cast<__half2*>(&r0.x));
        float2 b0 = __half22float2(*reinterpret_cast<__half2*>(&r0.y));
        float2 a1 = __half22float2(*reinterpret_cast<__half2*>(&r1.x));
        float2 b1 = __half22float2(*reinterpret_cast<__half2*>(&r1.y));
        float2 a2 = __half22float2(*reinterpret_cast<__half2*>(&r2.x));
        float2 b2 = __half22float2(*reinterpret_cast<__half2*>(&r2.y));
        float2 a3 = __half22float2(*reinterpret_cast<__half2*>(&r3.x));
        float2 b3 = __half22float2(*reinterpret_cast<__half2*>(&r3.y));
        acc.x += (a0.x + a1.x) + (a2.x + a3.x);
        acc.y += (a0.y + a1.y) + (a2.y + a3.y);
        acc.z += (b0.x + b1.x) + (b2.x + b3.x);
        acc.w += (b0.y + b1.y) + (b2.y + b3.y);
    }
    for (; i < rs1; i++) {
        int s0 = g_csrc[i];
        uint2 r0 = __ldg(reinterpret_cast<const uint2*>(h16 + (size_t)s0 * HID) + lane);
        float2 a0 = __half22float2(*reinterpret_cast<__half2*>(&r0.x));
        float2 b0 = __half22float2(*reinterpret_cast<__half2*>(&r0.y));
        acc.x += a0.x; acc.y += a0.y; acc.z += b0.x; acc.w += b0.y;
    }
    float sc = 1.0f / (float)max(rs1 - rs0, 1);
    acc.x *= sc; acc.y *= sc; acc.z *= sc; acc.w *= sc;
    reinterpret_cast<float4*>(agg + (size_t)n * HID)[lane] = acc;
}

__global__ void gather16_kernel(const float* __restrict__ x, float* __restrict__ agg, int M) {
    int gt = blockIdx.x * blockDim.x + threadIdx.x;
    int n = gt >> 2;
    if (n >= M) return;
    int q = gt & 3;
    int rs0 = g_rowstart[n], rs1 = g_rowstart[n + 1];
    float4 acc = make_float4(0.f, 0.f, 0.f, 0.f);
    for (int i = rs0; i < rs1; i++) {
        int s0 = g_csrc[i];
        float4 v = __ldg(reinterpret_cast<const float4*>(x + (size_t)s0 * INDIM) + q);
        acc.x += v.x; acc.y += v.y; acc.z += v.z; acc.w += v.w;
    }
    float sc = 1.0f / (float)max(rs1 - rs0, 1);
    acc.x *= sc; acc.y *= sc; acc.z *= sc; acc.w *= sc;
    reinterpret_cast<float4*>(agg + (size_t)n * INDIM)[q] = acc;
}

// ================= layer-1 tensor GEMM (K=32) via mma.sync =================
__global__ void __launch_bounds__(256)
tensor_l1_kernel(const float* __restrict__ agg, const float* __restrict__ x,
                 const __nv_bfloat16* __restrict__ WHi, const __nv_bfloat16* __restrict__ WLo,
                 const float* __restrict__ bias, float* __restrict__ C,
                 __half* __restrict__ C16, int M) {
    __shared__ __nv_bfloat16 sAhi[128 * TSTRIDE];
    __shared__ __nv_bfloat16 sAlo[128 * TSTRIDE];
    __shared__ __nv_bfloat16 sBhi[128 * TSTRIDE];
    __shared__ __nv_bfloat16 sBlo[128 * TSTRIDE];

    const int tid = threadIdx.x;
    const int wid = tid >> 5;
    const int lane = tid & 31;
    const int wm = wid & 3;
    const int wn = wid >> 2;
    const int m0 = blockIdx.x * 128;

    // ---- stage A: [agg | x] 128 x 32 (fp32 -> bf16 hi/lo) ----
    {
        int row = tid >> 1;
        int half = tid & 1;
        const float* src = half ? x : agg;
        int node = m0 + row;
        float4 v[4];
#pragma unroll
        for (int i = 0; i < 4; i++) v[i] = make_float4(0.f, 0.f, 0.f, 0.f);
        if (node < M) {
            const float4* p = reinterpret_cast<const float4*>(src + (size_t)node * INDIM);
#pragma unroll
            for (int i = 0; i < 4; i++) v[i] = p[i];
        }
        int so = row * TSTRIDE + half * 16;
#pragma unroll
        for (int i = 0; i < 4; i++) {
            __nv_bfloat16 h0, l0, h1, l1, h2, l2, h3, l3;
            split2(v[i].x, h0, l0);
            split2(v[i].y, h1, l1);
            split2(v[i].z, h2, l2);
            split2(v[i].w, h3, l3);
            uint2 ph, pl;
            ph.x = pack2(h0, h1); ph.y = pack2(h2, h3);
            pl.x = pack2(l0, l1); pl.y = pack2(l2, l3);
            *reinterpret_cast<uint2*>(sAhi + so + i * 4) = ph;
            *reinterpret_cast<uint2*>(sAlo + so + i * 4) = pl;
        }
    }
    // ---- stage B: [Wl1 | Wr1] 128 x 32 (pre-split bf16) ----
    {
        int row = tid >> 1;
        int half = tid & 1;
        const __nv_bfloat16* WH = WHi + half * 2048;
        const __nv_bfloat16* WL = WLo + half * 2048;
        int so = row * TSTRIDE + half * 16;
        uint4 h0 = *reinterpret_cast<const uint4*>(WH + row * 16);
        uint4 h1 = *reinterpret_cast<const uint4*>(WH + row * 16 + 8);
        uint4 l0 = *reinterpret_cast<const uint4*>(WL + row * 16);
        uint4 l1 = *reinterpret_cast<const uint4*>(WL + row * 16 + 8);
        *reinterpret_cast<uint4*>(sBhi + so) = h0;
        *reinterpret_cast<uint4*>(sBhi + so + 8) = h1;
        *reinterpret_cast<uint4*>(sBlo + so) = l0;
        *reinterpret_cast<uint4*>(sBlo + so + 8) = l1;
    }
    __syncthreads();

    const uint32_t uAhi = smem_u32(sAhi);
    const uint32_t uAlo = smem_u32(sAlo);
    const uint32_t uBhi = smem_u32(sBhi);
    const uint32_t uBlo = smem_u32(sBlo);

    float acc[2][8][4];
#pragma unroll
    for (int i = 0; i < 2; i++)
#pragma unroll
        for (int j = 0; j < 8; j++)
#pragma unroll
            for (int k = 0; k < 4; k++) acc[i][j][k] = 0.f;

    const int arow = wm * 32 + (lane & 15);
    const int akof = (lane & 16) ? 8 : 0;
    const int nrow0 = wn * 64 + (lane & 7) + ((lane & 16) ? 8 : 0);
    const int nkof = (lane & 8) ? 8 : 0;

#pragma unroll
    for (int ks = 0; ks < 2; ks++) {
        const int k0 = ks * 16;
        uint32_t ahi[2][4], alo[2][4];
#pragma unroll
        for (int mi = 0; mi < 2; mi++) {
            uint32_t off = ((arow + mi * 16) * TSTRIDE + k0 + akof) * 2;
            LDMX4(ahi[mi], uAhi + off);
            LDMX4(alo[mi], uAlo + off);
        }
#pragma unroll
        for (int np = 0; np < 4; np++) {
            uint32_t boff = ((nrow0 + np * 16) * TSTRIDE + k0 + nkof) * 2;
            uint32_t bh4[4], bl4[4];
            LDMX4(bh4, uBhi + boff);
            LDMX4(bl4, uBlo + boff);
#pragma unroll
            for (int mi = 0; mi < 2; mi++) {
#pragma unroll
                for (int na = 0; na < 2; na++) {
                    float* c = acc[mi][np * 2 + na];
                    mma16816(c, ahi[mi], &bh4[na * 2]);
                    mma16816(c, ahi[mi], &bl4[na * 2]);
                    mma16816(c, alo[mi], &bh4[na * 2]);
                }
            }
        }
    }

#pragma unroll
    for (int mi = 0; mi < 2; mi++) {
        int row0 = m0 + wm * 32 + mi * 16 + (lane >> 2);
        int row1 = row0 + 8;
#pragma unroll
        for (int ni = 0; ni < 8; ni++) {
            int col = wn * 64 + ni * 8 + 2 * (lane & 3);
            float b0 = __ldg(bias + col);
            float b1 = __ldg(bias + col + 1);
            float* c = acc[mi][ni];
            if (row0 < M) {
                float2 v;
                v.x = fmaxf(c[0] + b0, 0.f);
                v.y = fmaxf(c[1] + b1, 0.f);
                *reinterpret_cast<float2*>(C + (size_t)row0 * HID + col) = v;
                *reinterpret_cast<__half2*>(C16 + (size_t)row0 * HID + col) =
                    __floats2half2_rn(v.x, v.y);
            }
            if (row1 < M) {
                float2 v;
                v.x = fmaxf(c[2] + b0, 0.f);
                v.y = fmaxf(c[3] + b1, 0.f);
                *reinterpret_cast<float2*>(C + (size_t)row1 * HID + col) = v;
                *reinterpret_cast<__half2*>(C16 + (size_t)row1 * HID + col) =
                    __floats2half2_rn(v.x, v.y);
            }
        }
    }
}

// ================= tensor-core SAGE GEMM (layers 2/3) via mma.sync =================
template <bool FINAL>
__global__ void __launch_bounds__(256)
tensor_sage_kernel(const float* __restrict__ A0, const float* __restrict__ A1,
                   const __nv_bfloat16* __restrict__ W0hi, const __nv_bfloat16* __restrict__ W0lo,
                   const __nv_bfloat16* __restrict__ W1hi, const __nv_bfloat16* __restrict__ W1lo,
                   const float* __restrict__ bias, float* __restrict__ C,
                   __half* __restrict__ C16,
                   const float* __restrict__ Wh, const float* __restrict__ bh,
                   float* __restrict__ out, int M) {
    __shared__ __nv_bfloat16 sAhi[128 * TSTRIDE];
    __shared__ __nv_bfloat16 sAlo[128 * TSTRIDE];
    __shared__ __nv_bfloat16 sBhi[128 * TSTRIDE];
    __shared__ __nv_bfloat16 sBlo[128 * TSTRIDE];
    __shared__ float sWh[OUTDIM * HID];
    __shared__ float sbh[OUTDIM];
    __shared__ float red[128 * 8];

    const int tid = threadIdx.x;
    const int wid = tid >> 5;
    const int lane = tid & 31;
    const int wm = wid & 3;
    const int wn = wid >> 2;
    const int m0 = blockIdx.x * 128;

    if (FINAL) {
        for (int u = tid; u < OUTDIM * HID; u += 256) sWh[u] = Wh[u];
        if (tid < OUTDIM) sbh[tid] = bh[tid];
    }

    const uint32_t uAhi = smem_u32(sAhi);
    const uint32_t uAlo = smem_u32(sAlo);
    const uint32_t uBhi = smem_u32(sBhi);
    const uint32_t uBlo = smem_u32(sBlo);

    float acc[2][8][4];
#pragma unroll
    for (int i = 0; i < 2; i++)
#pragma unroll
        for (int j = 0; j < 8; j++)
#pragma unroll
            for (int k = 0; k < 4; k++) acc[i][j][k] = 0.f;

    const int arow = wm * 32 + (lane & 15);
    const int akof = (lane & 16) ? 8 : 0;
    const int nrow0 = wn * 64 + (lane & 7) + ((lane & 16) ? 8 : 0);
    const int nkof = (lane & 8) ? 8 : 0;

#pragma unroll
    for (int chunk = 0; chunk < 8; chunk++) {
        const float* A = (chunk < 4) ? A0 : A1;
        const __nv_bfloat16* WH = (chunk < 4) ? W0hi : W1hi;
        const __nv_bfloat16* WL = (chunk < 4) ? W0lo : W1lo;
        const int koff = (chunk & 3) * 32;

        __syncthreads();
#pragma unroll
        for (int i = 0; i < 4; i++) {
            int u = tid + i * 256;
            int row = u >> 3;
            int q = (u & 7) * 4;
            float4 v = make_float4(0.f, 0.f, 0.f, 0.f);
            int node = m0 + row;
            if (node < M)
                v = *reinterpret_cast<const float4*>(A + (size_t)node * HID + koff + q);
            __nv_bfloat16 h0, l0, h1, l1, h2, l2, h3, l3;
            split2(v.x, h0, l0);
            split2(v.y, h1, l1);
            split2(v.z, h2, l2);
            split2(v.w, h3, l3);
            int so = row * TSTRIDE + q;
            uint2 ph, pl;
            ph.x = pack2(h0, h1); ph.y = pack2(h2, h3);
            pl.x = pack2(l0, l1); pl.y = pack2(l2, l3);
            *reinterpret_cast<uint2*>(sAhi + so) = ph;
            *reinterpret_cast<uint2*>(sAlo + so) = pl;
        }
#pragma unroll
        for (int i = 0; i < 2; i++) {
            int u = tid + i * 256;
            int row = u >> 2;
            int c = (u & 3) * 8;
            uint4 vh = *reinterpret_cast<const uint4*>(WH + (size_t)row * HID + koff + c);
            uint4 vl = *reinterpret_cast<const uint4*>(WL + (size_t)row * HID + koff + c);
            int so = row * TSTRIDE + c;
            *reinterpret_cast<uint4*>(sBhi + so) = vh;
            *reinterpret_cast<uint4*>(sBlo + so) = vl;
        }
        __syncthreads();

#pragma unroll
        for (int ks = 0; ks < 2; ks++) {
            const int k0 = ks * 16;
            uint32_t ahi[2][4], alo[2][4];
#pragma unroll
            for (int mi = 0; mi < 2; mi++) {
                uint32_t off = ((arow + mi * 16) * TSTRIDE + k0 + akof) * 2;
                LDMX4(ahi[mi], uAhi + off);
                LDMX4(alo[mi], uAlo + off);
            }
#pragma unroll
            for (int np = 0; np < 4; np++) {
                uint32_t boff = ((nrow0 + np * 16) * TSTRIDE + k0 + nkof) * 2;
                uint32_t bh4[4], bl4[4];
                LDMX4(bh4, uBhi + boff);
                LDMX4(bl4, uBlo + boff);
#pragma unroll
                for (int mi = 0; mi < 2; mi++) {
#pragma unroll
                    for (int na = 0; na < 2; na++) {
                        float* c = acc[mi][np * 2 + na];
                        mma16816(c, ahi[mi], &bh4[na * 2]);
                        mma16816(c, ahi[mi], &bl4[na * 2]);
                        mma16816(c, alo[mi], &bh4[na * 2]);
                    }
                }
            }
        }
    }

    if (!FINAL) {
#pragma unroll
        for (int mi = 0; mi < 2; mi++) {
            int row0 = m0 + wm * 32 + mi * 16 + (lane >> 2);
            int row1 = row0 + 8;
#pragma unroll
            for (int ni = 0; ni < 8; ni++) {
                int col = wn * 64 + ni * 8 + 2 * (lane & 3);
                float b0 = __ldg(bias + col);
                float b1 = __ldg(bias + col + 1);
                float* c = acc[mi][ni];
                if (row0 < M) {
                    float2 v;
                    v.x = fmaxf(c[0] + b0, 0.f);
                    v.y = fmaxf(c[1] + b1, 0.f);
                    *reinterpret_cast<float2*>(C + (size_t)row0 * HID + col) = v;
                    *reinterpret_cast<__half2*>(C16 + (size_t)row0 * HID + col) =
                        __floats2half2_rn(v.x, v.y);
                }
                if (row1 < M) {
                    float2 v;
                    v.x = fmaxf(c[2] + b0, 0.f);
                    v.y = fmaxf(c[3] + b1, 0.f);
                    *reinterpret_cast<float2*>(C + (size_t)row1 * HID + col) = v;
                    *reinterpret_cast<__half2*>(C16 + (size_t)row1 * HID + col) =
                        __floats2half2_rn(v.x, v.y);
                }
            }
        }
    } else {
#pragma unroll
        for (int mi = 0; mi < 2; mi++) {
            float p0[OUTDIM] = {0.f, 0.f, 0.f, 0.f};
            float p1[OUTDIM] = {0.f, 0.f, 0.f, 0.f};
#pragma unroll
            for (int ni = 0; ni < 8; ni++) {
                int col = wn * 64 + ni * 8 + 2 * (lane & 3);
                float b0 = __ldg(bias + col);
                float b1 = __ldg(bias + col + 1);
                float* c = acc[mi][ni];
                float v0 = fmaxf(c[0] + b0, 0.f);
                float v1 = fmaxf(c[1] + b1, 0.f);
                float v2 = fmaxf(c[2] + b0, 0.f);
                float v3 = fmaxf(c[3] + b1, 0.f);
#pragma unroll
                for (int j = 0; j < OUTDIM; j++) {
                    float w0 = sWh[j * HID + col];
                    float w1 = sWh[j * HID + col + 1];
                    p0[j] += v0 * w0 + v1 * w1;
                    p1[j] += v2 * w0 + v3 * w1;
                }
            }
#pragma unroll
            for (int j = 0; j < OUTDIM; j++) {
                p0[j] += __shfl_xor_sync(0xffffffffu, p0[j], 1);
                p0[j] += __shfl_xor_sync(0xffffffffu, p0[j], 2);
                p1[j] += __shfl_xor_sync(0xffffffffu, p1[j], 1);
                p1[j] += __shfl_xor_sync(0xffffffffu, p1[j], 2);
            }
            if ((lane & 3) == 0) {
                int r0 = wm * 32 + mi * 16 + (lane >> 2);
                int r1 = r0 + 8;
#pragma unroll
                for (int j = 0; j < OUTDIM; j++) {
                    red[r0 * 8 + j * 2 + wn] = p0[j];
                    red[r1 * 8 + j * 2 + wn] = p1[j];
                }
            }
        }
        __syncthreads();
        for (int u = tid; u < 128 * OUTDIM; u += 256) {
            int row = u >> 2;
            int j = u & 3;
            int node = m0 + row;
            if (node < M)
                out[(size_t)node * OUTDIM + j] =
                    red[row * 8 + j * 2 + 0] + red[row * 8 + j * 2 + 1] + sbh[j];
        }
    }
}

// ---------------------------------------------------------------
extern "C" void kernel_launch(void* const* d_in, const int* in_sizes, int n_in,
                              void* d_out, int out_size) {
    (void)n_in; (void)out_size;
    const float* x   = (const float*)d_in[0];
    const int*   ei  = (const int*)d_in[1];
    const float* Wl1 = (const float*)d_in[2];
    const float* Wr1 = (const float*)d_in[3];
    const float* b1  = (const float*)d_in[4];
    const float* Wl2 = (const float*)d_in[5];
    const float* Wr2 = (const float*)d_in[6];
    const float* b2  = (const float*)d_in[7];
    const float* Wl3 = (const float*)d_in[8];
    const float* Wr3 = (const float*)d_in[9];
    const float* b3  = (const float*)d_in[10];
    const float* Wh  = (const float*)d_in[11];
    const float* bh  = (const float*)d_in[12];
    float* out = (float*)d_out;

    const int M = in_sizes[0] / INDIM;   // 50000
    const int E = in_sizes[1] / 2;       // 600000

    float *agg, *hA, *hB;
    __half *hA16, *hB16;
    __nv_bfloat16 *wHi, *wLo;
    cudaGetSymbolAddress((void**)&agg, g_agg);
    cudaGetSymbolAddress((void**)&hA, g_hA);
    cudaGetSymbolAddress((void**)&hB, g_hB);
    cudaGetSymbolAddress((void**)&hA16, g_hA16);
    cudaGetSymbolAddress((void**)&hB16, g_hB16);
    cudaGetSymbolAddress((void**)&wHi, g_wHi);
    cudaGetSymbolAddress((void**)&wLo, g_wLo);

    const int T = 256;
    const int NB = (M + SCAN_CHUNK - 1) / SCAN_CHUNK;

    // ---- CSR build ----
    init_kernel<<<(M + T - 1) / T, T>>>(ei, M);
    convert_kernel<<<(E + T - 1) / T, T>>>(ei, E);
    scan_phase1<<<NB, 256>>>(M);
    scan_phase3<<<NB, 256>>>(M, E, NB);
    fill_kernel<<<(E + T - 1) / T, T>>>(E);

    // ---- weight splits (all 6 in one launch) ----
    wsplit_all_kernel<<<(WTOT + T - 1) / T, T>>>(Wl2, Wr2, Wl3, Wr3, Wl1, Wr1);

    const int gemmBlocks = (M + 127) / 128;

    // ---- layer 1 (16 -> 128), mma.sync ----
    gather16_kernel<<<((M * 4) + T - 1) / T, T>>>(x, agg, M);
    tensor_l1_kernel<<<gemmBlocks, 256>>>(agg, x, wHi + W1L_OFF, wLo + W1L_OFF, b1, hA, hA16, M);

    // ---- layer 2 (128 -> 128), mma.sync ----
    gather128_f16<<<((M * 32) + T - 1) / T, T>>>(hA16, agg, M);
    tensor_sage_kernel<false><<<gemmBlocks, 256>>>(agg, hA,
        wHi + W2L_OFF, wLo + W2L_OFF, wHi + W2R_OFF, wLo + W2R_OFF,
        b2, hB, hB16, nullptr, nullptr, nullptr, M);

    // ---- layer 3 (128 -> 128) + fused final projection ----
    gather128_f16<<<((M * 32) + T - 1) / T, T>>>(hB16, agg, M);
    tensor_sage_kernel<true><<<gemmBlocks, 256>>>(agg, hB,
        wHi + W3L_OFF, wLo + W3L_OFF, wHi + W3R_OFF, wLo + W3R_OFF,
        b3, nullptr, nullptr, Wh, bh, out, M);
}